// round 13
// baseline (speedup 1.0000x reference)
#include <cuda_runtime.h>
#include <math.h>
#include <stdint.h>

#define B 16
#define N 1024
#define BN (B*N)
#define IN 128
#define H 32
#define KC 32
#define KM 16
#define MAXD 128
#define EPSV 1e-15f
#define FULL 0xffffffffu

// ---------------- accumulator slab (atomically accumulated; zeroed per run) --
#define ACC_NUMRW 0                    // [B]
#define ACC_DENRW 16                   // [B]
#define ACC_S00   32                   // [B]
#define ACC_S01   48                   // [B]
#define ACC_S11   64                   // [B]
#define ACC_SAS   80                   // [B]
#define ACC_DENCT 96                   // [B]
#define ACC_SDS   112                  // [B]
#define ACC_VOL   128                  // [B]
#define ACC_SSCT  144                  // [B][32*32]
#define ACC_OA    (ACC_SSCT+B*1024)    // [2][B][256]
#define ACC_SSP   (ACC_OA+2*B*256)     // [2][B][256]
#define ACC_PX    (ACC_SSP+2*B*256)    // [2][B][512]
#define ACC_DENP  (ACC_PX+2*B*512)     // [2][B]
#define ACC_LOSS  (ACC_DENP+2*B)       // [2] main, ortho
#define ACC_TOTAL (ACC_LOSS+2)

__device__ float g_acc[ACC_TOTAL];

// ---------------- scratch ----------------------------------------------------
__device__ float g_xh[BN*H];
__device__ int   g_cols[BN*MAXD];
__device__ int   g_deg[BN];
__device__ float g_srw[BN*2];
__device__ float4 g_ninfo[BN];        // {srw0, srw1, sqct, 0} packed per node
__device__ float g_sct[BN*KC];
__device__ float g_sqct[BN];
__device__ float g_wgap[BN*MAXD];
__device__ float g_wct[BN*MAXD];
__device__ float g_xg[2*BN*H];
__device__ float g_smc[2*BN*KM];
__device__ float g_x2[2*B*KM*H];

__device__ __forceinline__ float wsum(float v){
    #pragma unroll
    for(int o=16;o;o>>=1) v += __shfl_xor_sync(FULL, v, o);
    return v;
}
__device__ __forceinline__ float wsum16(float v){
    #pragma unroll
    for(int o=8;o;o>>=1) v += __shfl_xor_sync(FULL, v, o, 16);
    return v;
}

__global__ void k_init(){
    int i = blockIdx.x*blockDim.x + threadIdx.x;
    if (i < ACC_TOTAL) g_acc[i] = 0.f;
}

// fused: neighbor lists (prefetched float4 + ballot compaction, MLP=8) + vol +
//        xh=x@W1+b1 + rewiring softmax(k=2) + CT softmax(k=32) + scalar partials
__global__ void k_build_soft(const float* __restrict__ adj, const float* __restrict__ x,
                             const float* __restrict__ W1,  const float* __restrict__ b1,
                             const float* __restrict__ Wrw, const float* __restrict__ brw,
                             const float* __restrict__ Wct, const float* __restrict__ bct){
    __shared__ float W1s[IN*H];      // 16 KB
    __shared__ float Wcts[H*KC];     // 4 KB
    __shared__ float svol[8];
    __shared__ float sh[6];
    for (int i = threadIdx.x; i < IN*H; i += blockDim.x) W1s[i] = W1[i];
    for (int i = threadIdx.x; i < H*KC; i += blockDim.x) Wcts[i] = Wct[i];
    if (threadIdx.x < 6) sh[threadIdx.x] = 0.f;
    __syncthreads();

    int wid = (blockIdx.x*blockDim.x + threadIdx.x) >> 5;
    int lane = threadIdx.x & 31;
    int wz = threadIdx.x >> 5;

    // ---- neighbor list: prefetch entire row (MLP=8), then compact ----
    const float4* row = (const float4*)(adj + (size_t)wid * N);
    int* cols = g_cols + (size_t)wid * MAXD;
    float4 v[8];
    #pragma unroll
    for (int i = 0; i < 8; i++) v[i] = row[i*32 + lane];
    int cnt = 0;
    #pragma unroll
    for (int i = 0; i < 8; i++){
        bool n0=v[i].x!=0.f, n1=v[i].y!=0.f, n2=v[i].z!=0.f, n3=v[i].w!=0.f;
        unsigned m0=__ballot_sync(FULL,n0), m1=__ballot_sync(FULL,n1);
        unsigned m2=__ballot_sync(FULL,n2), m3=__ballot_sync(FULL,n3);
        unsigned below = (1u<<lane) - 1u;
        int idx = cnt + __popc(m0&below)+__popc(m1&below)+__popc(m2&below)+__popc(m3&below);
        int col0 = i*128 + lane*4;
        if(n0 && idx<MAXD){ cols[idx]=col0;   idx++; }
        if(n1 && idx<MAXD){ cols[idx]=col0+1; idx++; }
        if(n2 && idx<MAXD){ cols[idx]=col0+2; idx++; }
        if(n3 && idx<MAXD){ cols[idx]=col0+3; idx++; }
        cnt += __popc(m0)+__popc(m1)+__popc(m2)+__popc(m3);
    }
    int deg = cnt < MAXD ? cnt : MAXD;
    if (lane == 0){ g_deg[wid] = deg; svol[wz] = (float)deg; }

    // ---- xh = x @ W1 + b1 (lane = h) ----
    float acc = b1[lane];
    const float* xr = x + (size_t)wid*IN;
    #pragma unroll
    for (int c = 0; c < 4; c++){
        float xv = xr[c*32 + lane];
        #pragma unroll
        for (int j = 0; j < 32; j++)
            acc += __shfl_sync(FULL, xv, j) * W1s[(c*32+j)*H + lane];
    }
    g_xh[wid*H + lane] = acc;

    // ---- rewiring softmax (k=2) ----
    float a0 = wsum(acc*Wrw[lane*2])   + brw[0];
    float a1 = wsum(acc*Wrw[lane*2+1]) + brw[1];
    float mm = fmaxf(a0,a1);
    float e0 = expf(a0-mm), e1 = expf(a1-mm);
    float inv = 1.f/(e0+e1);
    float s0 = e0*inv, s1 = e1*inv;
    if (lane == 0){ g_srw[2*wid]=s0; g_srw[2*wid+1]=s1; }

    // ---- CT softmax (k=32, lane = k) ----
    float a = bct[lane];
    #pragma unroll
    for (int j = 0; j < 32; j++)
        a += __shfl_sync(FULL, acc, j) * Wcts[j*KC + lane];
    float m = a;
    #pragma unroll
    for (int o = 16; o; o >>= 1) m = fmaxf(m, __shfl_xor_sync(FULL, m, o));
    float e = expf(a - m);
    float s = e / wsum(e);
    g_sct[wid*KC + lane] = s;
    float sq = wsum(s*s);
    if (lane == 0){
        g_sqct[wid] = sq;
        g_ninfo[wid] = make_float4(s0, s1, sq, 0.f);
    }

    // ---- per-batch scalar partials ----
    if (lane == 0){
        atomicAdd(&sh[0], (float)deg*(s0*s0 + s1*s1)); // den_rw
        atomicAdd(&sh[1], s0*s0);                      // s00
        atomicAdd(&sh[2], s0*s1);                      // s01
        atomicAdd(&sh[3], s1*s1);                      // s11
        atomicAdd(&sh[4], sq);                         // den_ct
        atomicAdd(&sh[5], (float)deg*sq);              // sds
    }
    __syncthreads();
    int b = blockIdx.x >> 7;
    if (threadIdx.x < 6){
        const int dst[6] = {ACC_DENRW, ACC_S00, ACC_S01, ACC_S11, ACC_DENCT, ACC_SDS};
        atomicAdd(&g_acc[dst[threadIdx.x] + b], sh[threadIdx.x]);
    }
    if (threadIdx.x == 0){
        float vs = 0.f;
        #pragma unroll
        for (int i = 0; i < 8; i++) vs += svol[i];
        atomicAdd(&g_acc[ACC_VOL + b], vs);
    }
}

// S^T S partials from smem tiles (128-node chunks)
__global__ void k_ctpart(){
    int b = blockIdx.x >> 3, c = blockIdx.x & 7;
    int t = threadIdx.x;   // 1024
    __shared__ float S[128][33];
    int n0 = (b*N + c*128)*KC;
    #pragma unroll
    for (int i = 0; i < 4; i++){
        int idx = t + i*1024;
        S[idx>>5][idx&31] = g_sct[n0 + idx];
    }
    __syncthreads();
    int k = t >> 5, l = t & 31;
    float ssv = 0.f;
    #pragma unroll 8
    for (int n = 0; n < 128; n++)
        ssv += S[n][k]*S[n][l];
    atomicAdd(&g_acc[ACC_SSCT + b*1024 + t], ssv);
}

// MEGA-FUSED edge kernel: 16-edge subtiles with DOUBLE-BUFFERED staging.
// Tile t+1's staging LDGs fly while tile t's dot+agg consume buffer t.
__global__ void __launch_bounds__(256, 5)
k_edgeagg(const float* __restrict__ Wr0, const float* __restrict__ br0,
          const float* __restrict__ Wo0, const float* __restrict__ Wm0,
          const float* __restrict__ bm0,
          const float* __restrict__ Wr1, const float* __restrict__ br1,
          const float* __restrict__ Wo1, const float* __restrict__ Wm1,
          const float* __restrict__ bm1){
    __shared__ float  S[8*2*16*36];                 // 36 KB double-buffered staging
    __shared__ float4 SN[8][8];                     // sn per warp (32 floats)
    __shared__ float4 WGC[8][16];                   // {wg, wc, mc, 0} per edge
    __shared__ float shred[4];                      // num, sas, denp0, denp1
    if (threadIdx.x < 4) shred[threadIdx.x] = 0.f;
    __syncthreads();

    int wid = (blockIdx.x*blockDim.x + threadIdx.x) >> 5;
    int lane = threadIdx.x & 31;
    int w = threadIdx.x >> 5;
    float* bufA = S + (w*2+0)*576;
    float* bufB = S + (w*2+1)*576;
    float4* wgc = WGC[w];
    int b = wid >> 10, bN = b << 10;
    int deg = g_deg[wid];
    const int* cols = g_cols + wid*MAXD;
    float f_n = g_srw[2*wid];
    float s1n = g_srw[2*wid+1];
    float sn  = g_sct[wid*KC + lane];
    float sqn = g_sqct[wid];
    float invvol = 1.f/(g_acc[ACC_VOL + b] + EPSV);
    float num_acc = 0.f, sas_acc = 0.f;
    float dg_acc = 0.f, dc_acc = 0.f;
    float y_gap = 0.f, y_ct = 0.f;         // lane = h

    // stage sn into smem once (read back as float4)
    ((float*)SN[w])[lane] = sn;
    __syncwarp();

    int r8 = lane >> 3;        // 0..3 : row group
    int p8 = lane & 7;         // 0..7 : float4 slot
    int eh = lane & 15;        // edge within subtile
    int half = lane >> 4;      // which 16 elements of the dot
    float4 sA0 = SN[w][half*4+0], sA1 = SN[w][half*4+1];
    float4 sB0 = SN[w][half*4+2], sB1 = SN[w][half*4+3];

    // prologue: stage tile 0 into bufA
    #pragma unroll
    for (int g = 0; g < 4; g++){
        int e = g*4 + r8;
        if (e < deg){
            int rm = bN + cols[e];
            float4 v = ((const float4*)(g_sct + (size_t)rm*KC))[p8];
            ((float4*)(bufA + e*36))[p8] = v;
        }
    }
    __syncwarp();

    float* cur = bufA;
    float* nxt = bufB;
    for (int j0 = 0; j0 < deg; j0 += 16){
        int tlen = deg - j0; if (tlen > 16) tlen = 16;
        // issue staging LDGs for tile t+1 into nxt (latency hidden under compute)
        if (j0 + 16 < deg){
            #pragma unroll
            for (int g = 0; g < 4; g++){
                int e = g*4 + r8;
                int j = j0 + 16 + e;
                if (j < deg){
                    int rm = bN + cols[j];
                    float4 v = ((const float4*)(g_sct + (size_t)rm*KC))[p8];
                    ((float4*)(nxt + e*36))[p8] = v;
                }
            }
        }
        // dot from cur
        int j = j0 + eh;
        bool act = j < deg;
        int mc = act ? cols[j] : 0;
        const float4* row4 = (const float4*)(cur + eh*36) + half*4;
        float4 va = row4[0], vb = row4[1], vc = row4[2], vd = row4[3];
        float dA = va.x*sA0.x + va.y*sA0.y + va.z*sA0.z + va.w*sA0.w
                 + vc.x*sB0.x + vc.y*sB0.y + vc.z*sB0.z + vc.w*sB0.w;
        float dB = vb.x*sA1.x + vb.y*sA1.y + vb.z*sA1.z + vb.w*sA1.w
                 + vd.x*sB1.x + vd.y*sB1.y + vd.z*sB1.z + vd.w*sB1.w;
        float dh = dA + dB;
        float dot = dh + __shfl_xor_sync(FULL, dh, 16);
        float wg = 0.f, wc = 0.f;
        if (act && half == 0){
            float4 ni = g_ninfo[bN + mc];
            float d = f_n - ni.x;
            float q2 = sqn + ni.z - 2.f*dot;
            wg = 1.f - d*d;
            wc = sqrtf(fmaxf(q2, 0.f) + 1e-12f)*invvol;
            g_wgap[wid*MAXD + j] = wg;
            g_wct [wid*MAXD + j] = wc;
            num_acc += f_n*ni.x + s1n*ni.y;
            sas_acc += dot;
        }
        dg_acc += wg; dc_acc += wc;
        if (half == 0) wgc[eh] = make_float4(wg, wc, __int_as_float(mc), 0.f);
        __syncwarp();
        // both-branch aggregation: broadcast LDS.128 + coalesced LDG, unroll 4
        #pragma unroll 4
        for (int jj = 0; jj < tlen; jj++){
            float4 q = wgc[jj];
            float xv = g_xh[(bN + __float_as_int(q.z))*H + lane];
            y_gap += q.x*xv;
            y_ct  += q.y*xv;
        }
        __syncwarp();
        float* tmp = cur; cur = nxt; nxt = tmp;
    }
    num_acc = wsum(num_acc);
    sas_acc = wsum(sas_acc);
    float dsum_g = wsum(dg_acc);
    float dsum_c = wsum(dc_acc);

    // lin + pool softmax for both branches (weights from global; L1-hit broadcast)
    float xh = g_xh[wid*H + lane];
    float den_g = 0.f, den_c = 0.f;
    #pragma unroll
    for (int br = 0; br < 2; br++){
        float y = br ? y_ct : y_gap;
        const float* brel = br ? br1 : br0;
        const float* bmc  = br ? bm1 : bm0;
        const float* Wr = br ? Wr1 : Wr0;
        const float* Wo = br ? Wo1 : Wo0;
        const float* Wm = br ? Wm1 : Wm0;
        float acc = brel[lane];
        #pragma unroll
        for (int j = 0; j < 32; j++){
            acc += __shfl_sync(FULL, y,  j) * Wr[j*H + lane];
            acc += __shfl_sync(FULL, xh, j) * Wo[j*H + lane];
        }
        g_xg[br*BN*H + wid*H + lane] = acc;
        float a = (lane < KM) ? bmc[lane] : 0.f;
        #pragma unroll
        for (int j = 0; j < 32; j++){
            float xj = __shfl_sync(FULL, acc, j);
            if (lane < KM) a += xj * Wm[j*KM + lane];
        }
        float mm = a;
        #pragma unroll
        for (int o = 8; o; o >>= 1) mm = fmaxf(mm, __shfl_xor_sync(FULL, mm, o, 16));
        float e = (lane < KM) ? expf(a - mm) : 0.f;
        float es = wsum16(e);
        float s = e/es;
        if (lane < KM) g_smc[br*BN*KM + wid*KM + lane] = s;
        float sq = wsum16(s*s);
        if (br) den_c = sq; else den_g = sq;
    }
    if (lane == 0){
        atomicAdd(&shred[0], num_acc);
        atomicAdd(&shred[1], sas_acc);
        atomicAdd(&shred[2], dsum_g*den_g);
        atomicAdd(&shred[3], dsum_c*den_c);
    }
    __syncthreads();
    if (threadIdx.x < 4){
        int bb = blockIdx.x >> 7;
        const int dst[4] = {ACC_NUMRW, ACC_SAS, ACC_DENP, ACC_DENP + B};
        atomicAdd(&g_acc[dst[threadIdx.x] + bb], shred[threadIdx.x]);
    }
}

// batch-staged pool: one block = (128-node chunk, batch, branch).
// Full batch smc (64KB) staged in DYNAMIC smem; t16 gathers hit shared memory.
__global__ void k_pool(){
    extern __shared__ float smc_s[];       // N*KM = 16384 floats = 64KB
    __shared__ float st16[128*17];
    int c = blockIdx.x, b = blockIdx.y, br = blockIdx.z;
    int t = threadIdx.x;                   // 1024
    int w = t >> 5, lane = t & 31;
    int bN = b*N;
    const float* smc = g_smc + br*BN*KM;
    {
        float4* dst = (float4*)smc_s;
        const float4* src = (const float4*)(smc + bN*KM);
        #pragma unroll
        for (int i = 0; i < 4; i++) dst[t + i*1024] = src[t + i*1024];
    }
    __syncthreads();
    int half = lane >> 4, l16 = lane & 15;
    #pragma unroll
    for (int q = 0; q < 4; q++){
        int nl = c*128 + w*4 + q;          // local node in batch
        int r = bN + nl;
        int deg = g_deg[r];
        const int* cols = g_cols + r*MAXD;
        const float* w_arr = (br ? g_wct : g_wgap) + r*MAXD;
        float tacc = 0.f;
        #pragma unroll 2
        for (int j = half; j < deg; j += 2)
            tacc += w_arr[j] * smc_s[cols[j]*KM + l16];
        tacc += __shfl_down_sync(FULL, tacc, 16);
        if (lane < KM) st16[(w*4+q)*17 + l16] = tacc;
    }
    __syncthreads();
    int base = (br*B + b)*256;
    int n0 = c*128;
    if (t < 256){
        int k = t >> 4, l = t & 15;
        float oa = 0.f;
        #pragma unroll 4
        for (int n = 0; n < 128; n++)
            oa += smc_s[(n0+n)*KM + k] * st16[n*17 + l];
        atomicAdd(&g_acc[ACC_OA + base + t], oa);
    } else if (t < 512){
        int k = (t-256) >> 4, l = t & 15;
        float ssv = 0.f;
        #pragma unroll 4
        for (int n = 0; n < 128; n++)
            ssv += smc_s[(n0+n)*KM + k] * smc_s[(n0+n)*KM + l];
        atomicAdd(&g_acc[ACC_SSP + base + (t-256)], ssv);
    } else {
        int kk = (t-512) >> 5, h = t & 31;
        float px = 0.f;
        const float* xg = g_xg + br*BN*H + (size_t)(bN + n0)*H;
        #pragma unroll 4
        for (int n = 0; n < 128; n++)
            px += smc_s[(n0+n)*KM + kk] * xg[n*H + h];
        atomicAdd(&g_acc[ACC_PX + (br*B + b)*512 + (t-512)], px);
    }
}

// finalize pool: pool losses + normalized pooladj + pooled DGC; br==0 blocks
// additionally compute the CT ortho/ct/rw losses (merged k_ctfin).
__global__ void k_poolfin(const float* __restrict__ W2g_rel, const float* __restrict__ b2g,
                          const float* __restrict__ W2g_root){
    int b = blockIdx.x, br = blockIdx.y, t = threadIdx.x;   // 512
    __shared__ float oa[256], ssm[256], px[512], t2[512], pa[256], red[512], nrm_s;
    int base = (br*B + b)*256;
    if (t < 256){ oa[t] = g_acc[ACC_OA + base + t]; ssm[t] = g_acc[ACC_SSP + base + t]; }
    px[t] = g_acc[ACC_PX + (br*B + b)*512 + t];
    __syncthreads();
    red[t] = (t < 256) ? ssm[t]*ssm[t] : 0.f;
    __syncthreads();
    for (int o = 256; o; o >>= 1){ if (t < o) red[t] += red[t+o]; __syncthreads(); }
    if (t == 0) nrm_s = sqrtf(red[0]);
    __syncthreads();
    if (t < 256){
        int k = t >> 4, l = t & 15;
        float d = ssm[t]/nrm_s - ((k == l) ? 0.25f : 0.f);
        red[t] = d*d;
    } else red[t] = 0.f;
    __syncthreads();
    for (int o = 256; o; o >>= 1){ if (t < o) red[t] += red[t+o]; __syncthreads(); }
    if (t == 0){
        float num = 0.f;
        #pragma unroll
        for (int k = 0; k < KM; k++) num += oa[k*KM + k];
        float den = g_acc[ACC_DENP + br*B + b] + EPSV;
        atomicAdd(&g_acc[ACC_LOSS],   -(num/den)/(float)B);
        atomicAdd(&g_acc[ACC_LOSS+1], sqrtf(red[0])/(float)B);
    }
    __shared__ float dsq[KM];
    if (t < KM){
        float rs = 0.f;
        #pragma unroll
        for (int l = 0; l < KM; l++) rs += (l == t) ? 0.f : oa[t*KM + l];
        dsq[t] = sqrtf(rs) + EPSV;
    }
    __syncthreads();
    if (t < 256){
        int k = t >> 4, l = t & 15;
        pa[t] = (k == l) ? 0.f : oa[t]/(dsq[k]*dsq[l]);
    }
    __syncthreads();
    int k = t >> 5, h = t & 31;
    float a = 0.f;
    #pragma unroll
    for (int l = 0; l < KM; l++) a += pa[k*KM + l]*px[l*H + h];
    t2[t] = a;
    __syncthreads();
    float accv = b2g[h];
    #pragma unroll
    for (int j = 0; j < H; j++)
        accv += t2[k*H + j]*W2g_rel[j*H + h] + px[k*H + j]*W2g_root[j*H + h];
    g_x2[br*B*KM*H + b*KM*H + t] = accv;

    // ---- merged CT/rewiring losses (br==0 blocks only) ----
    if (br == 0){
        __syncthreads();
        float v1 = g_acc[ACC_SSCT + b*1024 + t];
        float v2 = g_acc[ACC_SSCT + b*1024 + t + 512];
        red[t] = v1*v1 + v2*v2;
        __syncthreads();
        for (int o = 256; o; o >>= 1){ if (t < o) red[t] += red[t+o]; __syncthreads(); }
        if (t == 0) nrm_s = sqrtf(red[0]);
        __syncthreads();
        float nrm = nrm_s;
        const float isk32 = 0.17677669529663687f;
        int e1 = t,       k1 = e1 >> 5, l1 = e1 & 31;
        int e2 = t + 512, k2 = e2 >> 5, l2 = e2 & 31;
        float d1 = v1/nrm - ((k1 == l1) ? isk32 : 0.f);
        float d2 = v2/nrm - ((k2 == l2) ? isk32 : 0.f);
        red[t] = d1*d1 + d2*d2;
        __syncthreads();
        for (int o = 256; o; o >>= 1){ if (t < o) red[t] += red[t+o]; __syncthreads(); }
        if (t == 0){
            float sas = g_acc[ACC_SAS + b];
            float den = g_acc[ACC_DENCT + b] + EPSV;
            float sds = g_acc[ACC_SDS + b];
            float lm = ((sds - sas)/den)/(float)B;
            float lo = sqrtf(red[0])/(float)B;
            float num = g_acc[ACC_NUMRW + b];
            float dnr = g_acc[ACC_DENRW + b] + EPSV;
            float s00 = g_acc[ACC_S00 + b];
            float s01 = g_acc[ACC_S01 + b];
            float s11 = g_acc[ACC_S11 + b];
            float nrm2 = sqrtf(s00*s00 + 2.f*s01*s01 + s11*s11);
            const float isk = 0.70710678118654752f;
            float d00 = s00/nrm2 - isk, d01 = s01/nrm2, d11 = s11/nrm2 - isk;
            lm += -(num/dnr)/(float)B;
            lo += sqrtf(d00*d00 + 2.f*d01*d01 + d11*d11)/(float)B;
            atomicAdd(&g_acc[ACC_LOSS],   lm);
            atomicAdd(&g_acc[ACC_LOSS+1], lo);
        }
    }
}

__global__ void k_readout(const float* __restrict__ Wcat, const float* __restrict__ bcat,
                          const float* __restrict__ W2,  const float* __restrict__ b2,
                          const float* __restrict__ W3,  const float* __restrict__ b3,
                          float* __restrict__ out){
    int b = blockIdx.x, h = threadIdx.x;   // 32
    __shared__ float h1[H], h2[H], lg[10];
    float acc = 0.f;
    for (int kk = 0; kk < KM; kk++){
        float z = bcat[h];
        #pragma unroll
        for (int j = 0; j < H; j++) z += g_x2[b*KM*H + kk*H + j]*Wcat[j*H + h];
        #pragma unroll
        for (int j = 0; j < H; j++) z += g_x2[B*KM*H + b*KM*H + kk*H + j]*Wcat[(H+j)*H + h];
        acc += fmaxf(z, 0.f);
    }
    h1[h] = acc; __syncwarp();
    float z2 = b2[h];
    #pragma unroll
    for (int j = 0; j < H; j++) z2 += h1[j]*W2[j*H + h];
    h2[h] = fmaxf(z2, 0.f); __syncwarp();
    if (h < 10){
        float z = b3[h];
        #pragma unroll
        for (int j = 0; j < H; j++) z += h2[j]*W3[j*10 + h];
        lg[h] = z;
    }
    __syncwarp();
    if (h < 10){
        float m = lg[0];
        #pragma unroll
        for (int i = 1; i < 10; i++) m = fmaxf(m, lg[i]);
        float s = 0.f;
        #pragma unroll
        for (int i = 0; i < 10; i++) s += expf(lg[i] - m);
        out[b*10 + h] = lg[h] - m - logf(s);
    }
    if (b == 0 && h == 31){
        out[B*10]     = g_acc[ACC_LOSS];
        out[B*10 + 1] = g_acc[ACC_LOSS+1];
    }
}

extern "C" void kernel_launch(void* const* d_in, const int* in_sizes, int n_in,
                              void* d_out, int out_size){
    const float* x      = (const float*)d_in[0];
    const float* adj    = (const float*)d_in[1];
    const float* W1     = (const float*)d_in[3];
    const float* b1     = (const float*)d_in[4];
    const float* Wrw    = (const float*)d_in[5];
    const float* brw    = (const float*)d_in[6];
    const float* Wg_rel = (const float*)d_in[7];
    const float* bg     = (const float*)d_in[8];
    const float* Wg_root= (const float*)d_in[9];
    const float* Wmcg   = (const float*)d_in[10];
    const float* bmcg   = (const float*)d_in[11];
    const float* W2g_rel= (const float*)d_in[12];
    const float* b2g    = (const float*)d_in[13];
    const float* W2g_root=(const float*)d_in[14];
    const float* Wct    = (const float*)d_in[15];
    const float* bct    = (const float*)d_in[16];
    const float* Wc_rel = (const float*)d_in[17];
    const float* bc     = (const float*)d_in[18];
    const float* Wc_root= (const float*)d_in[19];
    const float* Wmcc   = (const float*)d_in[20];
    const float* bmcc   = (const float*)d_in[21];
    const float* Wcat   = (const float*)d_in[22];
    const float* bcat   = (const float*)d_in[23];
    const float* W2     = (const float*)d_in[24];
    const float* b2     = (const float*)d_in[25];
    const float* W3     = (const float*)d_in[26];
    const float* b3     = (const float*)d_in[27];
    float* out = (float*)d_out;

    cudaFuncSetAttribute(k_pool, cudaFuncAttributeMaxDynamicSharedMemorySize, 65536);

    k_init<<<(ACC_TOTAL+511)/512, 512>>>();
    k_build_soft<<<BN/8, 256>>>(adj, x, W1, b1, Wrw, brw, Wct, bct);
    k_ctpart<<<B*8, 1024>>>();
    k_edgeagg<<<BN/8, 256>>>(Wg_rel, bg, Wg_root, Wmcg, bmcg,
                             Wc_rel, bc, Wc_root, Wmcc, bmcc);
    k_pool<<<dim3(8, B, 2), 1024, 65536>>>();
    k_poolfin<<<dim3(B, 2), 512>>>(W2g_rel, b2g, W2g_root);
    k_readout<<<B, 32>>>(Wcat, bcat, W2, b2, W3, b3, out);

    (void)in_sizes; (void)n_in; (void)out_size;
}

// round 14
// speedup vs baseline: 1.0622x; 1.0622x over previous
#include <cuda_runtime.h>
#include <math.h>
#include <stdint.h>

#define B 16
#define N 1024
#define BN (B*N)
#define IN 128
#define H 32
#define KC 32
#define KM 16
#define MAXD 128
#define EPSV 1e-15f
#define FULL 0xffffffffu

// ---------------- accumulator slab (atomically accumulated; zeroed per run) --
#define ACC_NUMRW 0                    // [B]
#define ACC_DENRW 16                   // [B]
#define ACC_S00   32                   // [B]
#define ACC_S01   48                   // [B]
#define ACC_S11   64                   // [B]
#define ACC_SAS   80                   // [B]
#define ACC_DENCT 96                   // [B]
#define ACC_SDS   112                  // [B]
#define ACC_VOL   128                  // [B]
#define ACC_SSCT  144                  // [B][32*32]
#define ACC_OA    (ACC_SSCT+B*1024)    // [2][B][256]
#define ACC_SSP   (ACC_OA+2*B*256)     // [2][B][256]
#define ACC_PX    (ACC_SSP+2*B*256)    // [2][B][512]
#define ACC_DENP  (ACC_PX+2*B*512)     // [2][B]
#define ACC_LOSS  (ACC_DENP+2*B)       // [2] main, ortho
#define ACC_TOTAL (ACC_LOSS+2)

__device__ float g_acc[ACC_TOTAL];

// ---------------- scratch ----------------------------------------------------
__device__ float g_xh[BN*H];
__device__ int   g_cols[BN*MAXD];
__device__ int   g_deg[BN];
__device__ float g_srw[BN*2];
__device__ float4 g_ninfo[BN];        // {srw0, srw1, sqct, 0} packed per node
__device__ float g_sct[BN*KC];
__device__ float g_sqct[BN];
__device__ float g_wgap[BN*MAXD];
__device__ float g_wct[BN*MAXD];
__device__ float g_xg[2*BN*H];
__device__ float g_smc[2*BN*KM];
__device__ float g_x2[2*B*KM*H];

__device__ __forceinline__ float wsum(float v){
    #pragma unroll
    for(int o=16;o;o>>=1) v += __shfl_xor_sync(FULL, v, o);
    return v;
}
__device__ __forceinline__ float wsum16(float v){
    #pragma unroll
    for(int o=8;o;o>>=1) v += __shfl_xor_sync(FULL, v, o, 16);
    return v;
}

__global__ void k_init(){
    int i = blockIdx.x*blockDim.x + threadIdx.x;
    if (i < ACC_TOTAL) g_acc[i] = 0.f;
}

// fused: neighbor lists (prefetched float4 + ballot compaction, MLP=8) + vol +
//        xh=x@W1+b1 + rewiring softmax(k=2) + CT softmax(k=32) + scalar partials
__global__ void k_build_soft(const float* __restrict__ adj, const float* __restrict__ x,
                             const float* __restrict__ W1,  const float* __restrict__ b1,
                             const float* __restrict__ Wrw, const float* __restrict__ brw,
                             const float* __restrict__ Wct, const float* __restrict__ bct){
    __shared__ float W1s[IN*H];      // 16 KB
    __shared__ float Wcts[H*KC];     // 4 KB
    __shared__ float svol[8];
    __shared__ float sh[6];
    for (int i = threadIdx.x; i < IN*H; i += blockDim.x) W1s[i] = W1[i];
    for (int i = threadIdx.x; i < H*KC; i += blockDim.x) Wcts[i] = Wct[i];
    if (threadIdx.x < 6) sh[threadIdx.x] = 0.f;
    __syncthreads();

    int wid = (blockIdx.x*blockDim.x + threadIdx.x) >> 5;
    int lane = threadIdx.x & 31;
    int wz = threadIdx.x >> 5;

    // ---- neighbor list: prefetch entire row (MLP=8), then compact ----
    const float4* row = (const float4*)(adj + (size_t)wid * N);
    int* cols = g_cols + (size_t)wid * MAXD;
    float4 v[8];
    #pragma unroll
    for (int i = 0; i < 8; i++) v[i] = row[i*32 + lane];
    int cnt = 0;
    #pragma unroll
    for (int i = 0; i < 8; i++){
        bool n0=v[i].x!=0.f, n1=v[i].y!=0.f, n2=v[i].z!=0.f, n3=v[i].w!=0.f;
        unsigned m0=__ballot_sync(FULL,n0), m1=__ballot_sync(FULL,n1);
        unsigned m2=__ballot_sync(FULL,n2), m3=__ballot_sync(FULL,n3);
        unsigned below = (1u<<lane) - 1u;
        int idx = cnt + __popc(m0&below)+__popc(m1&below)+__popc(m2&below)+__popc(m3&below);
        int col0 = i*128 + lane*4;
        if(n0 && idx<MAXD){ cols[idx]=col0;   idx++; }
        if(n1 && idx<MAXD){ cols[idx]=col0+1; idx++; }
        if(n2 && idx<MAXD){ cols[idx]=col0+2; idx++; }
        if(n3 && idx<MAXD){ cols[idx]=col0+3; idx++; }
        cnt += __popc(m0)+__popc(m1)+__popc(m2)+__popc(m3);
    }
    int deg = cnt < MAXD ? cnt : MAXD;
    if (lane == 0){ g_deg[wid] = deg; svol[wz] = (float)deg; }

    // ---- xh = x @ W1 + b1 (lane = h) ----
    float acc = b1[lane];
    const float* xr = x + (size_t)wid*IN;
    #pragma unroll
    for (int c = 0; c < 4; c++){
        float xv = xr[c*32 + lane];
        #pragma unroll
        for (int j = 0; j < 32; j++)
            acc += __shfl_sync(FULL, xv, j) * W1s[(c*32+j)*H + lane];
    }
    g_xh[wid*H + lane] = acc;

    // ---- rewiring softmax (k=2) ----
    float a0 = wsum(acc*Wrw[lane*2])   + brw[0];
    float a1 = wsum(acc*Wrw[lane*2+1]) + brw[1];
    float mm = fmaxf(a0,a1);
    float e0 = expf(a0-mm), e1 = expf(a1-mm);
    float inv = 1.f/(e0+e1);
    float s0 = e0*inv, s1 = e1*inv;
    if (lane == 0){ g_srw[2*wid]=s0; g_srw[2*wid+1]=s1; }

    // ---- CT softmax (k=32, lane = k) ----
    float a = bct[lane];
    #pragma unroll
    for (int j = 0; j < 32; j++)
        a += __shfl_sync(FULL, acc, j) * Wcts[j*KC + lane];
    float m = a;
    #pragma unroll
    for (int o = 16; o; o >>= 1) m = fmaxf(m, __shfl_xor_sync(FULL, m, o));
    float e = expf(a - m);
    float s = e / wsum(e);
    g_sct[wid*KC + lane] = s;
    float sq = wsum(s*s);
    if (lane == 0){
        g_sqct[wid] = sq;
        g_ninfo[wid] = make_float4(s0, s1, sq, 0.f);
    }

    // ---- per-batch scalar partials ----
    if (lane == 0){
        atomicAdd(&sh[0], (float)deg*(s0*s0 + s1*s1)); // den_rw
        atomicAdd(&sh[1], s0*s0);                      // s00
        atomicAdd(&sh[2], s0*s1);                      // s01
        atomicAdd(&sh[3], s1*s1);                      // s11
        atomicAdd(&sh[4], sq);                         // den_ct
        atomicAdd(&sh[5], (float)deg*sq);              // sds
    }
    __syncthreads();
    int b = blockIdx.x >> 7;
    if (threadIdx.x < 6){
        const int dst[6] = {ACC_DENRW, ACC_S00, ACC_S01, ACC_S11, ACC_DENCT, ACC_SDS};
        atomicAdd(&g_acc[dst[threadIdx.x] + b], sh[threadIdx.x]);
    }
    if (threadIdx.x == 0){
        float vs = 0.f;
        #pragma unroll
        for (int i = 0; i < 8; i++) vs += svol[i];
        atomicAdd(&g_acc[ACC_VOL + b], vs);
    }
}

// S^T S partials from smem tiles (128-node chunks)
__global__ void k_ctpart(){
    int b = blockIdx.x >> 3, c = blockIdx.x & 7;
    int t = threadIdx.x;   // 1024
    __shared__ float S[128][33];
    int n0 = (b*N + c*128)*KC;
    #pragma unroll
    for (int i = 0; i < 4; i++){
        int idx = t + i*1024;
        S[idx>>5][idx&31] = g_sct[n0 + idx];
    }
    __syncthreads();
    int k = t >> 5, l = t & 31;
    float ssv = 0.f;
    #pragma unroll 8
    for (int n = 0; n < 128; n++)
        ssv += S[n][k]*S[n][l];
    atomicAdd(&g_acc[ACC_SSCT + b*1024 + t], ssv);
}

// MEGA-FUSED edge kernel (R12 design: single-buffer 16-edge staged subtiles),
// weights read from global in the tail (L1-hit broadcast) => smem ~22KB.
__global__ void __launch_bounds__(256, 6)
k_edgeagg(const float* __restrict__ Wr0, const float* __restrict__ br0,
          const float* __restrict__ Wo0, const float* __restrict__ Wm0,
          const float* __restrict__ bm0,
          const float* __restrict__ Wr1, const float* __restrict__ br1,
          const float* __restrict__ Wo1, const float* __restrict__ Wm1,
          const float* __restrict__ bm1){
    __shared__ float  S[8*16*36];                   // 18 KB row staging
    __shared__ float4 SN[8][8];                     // sn per warp (32 floats)
    __shared__ float4 WGC[8][16];                   // {wg, wc, mc, 0} per edge
    __shared__ float shred[4];                      // num, sas, denp0, denp1
    if (threadIdx.x < 4) shred[threadIdx.x] = 0.f;
    __syncthreads();

    int wid = (blockIdx.x*blockDim.x + threadIdx.x) >> 5;
    int lane = threadIdx.x & 31;
    int w = threadIdx.x >> 5;
    float* Sw = S + w*16*36;
    float4* wgc = WGC[w];
    int b = wid >> 10, bN = b << 10;
    int deg = g_deg[wid];
    const int* cols = g_cols + wid*MAXD;
    float f_n = g_srw[2*wid];
    float s1n = g_srw[2*wid+1];
    float sn  = g_sct[wid*KC + lane];
    float sqn = g_sqct[wid];
    float invvol = 1.f/(g_acc[ACC_VOL + b] + EPSV);
    float num_acc = 0.f, sas_acc = 0.f;
    float dg_acc = 0.f, dc_acc = 0.f;
    float y_gap = 0.f, y_ct = 0.f;         // lane = h

    // stage sn into smem once (read back as float4)
    ((float*)SN[w])[lane] = sn;
    __syncwarp();

    int r8 = lane >> 3;        // 0..3 : row group
    int p8 = lane & 7;         // 0..7 : float4 slot
    int eh = lane & 15;        // edge within subtile
    int half = lane >> 4;      // which 16 elements of the dot

    for (int j0 = 0; j0 < deg; j0 += 16){
        int tlen = deg - j0; if (tlen > 16) tlen = 16;
        // cooperative vectorized staging of up to 16 neighbor sct rows
        #pragma unroll
        for (int g = 0; g < 4; g++){
            int e = g*4 + r8;
            int j = j0 + e;
            if (j < deg){
                int rm = bN + cols[j];
                float4 v = ((const float4*)(g_sct + (size_t)rm*KC))[p8];
                ((float4*)(Sw + e*36))[p8] = v;
            }
        }
        __syncwarp();
        int j = j0 + eh;
        bool act = j < deg;
        int mc = act ? cols[j] : 0;
        const float4* row4 = (const float4*)(Sw + eh*36) + half*4;
        const float4* sn4  = SN[w] + half*4;
        float dA = 0.f, dB = 0.f;
        #pragma unroll
        for (int q = 0; q < 2; q++){
            float4 va = row4[2*q],   sa = sn4[2*q];
            float4 vb = row4[2*q+1], sb = sn4[2*q+1];
            dA += va.x*sa.x + va.y*sa.y + va.z*sa.z + va.w*sa.w;
            dB += vb.x*sb.x + vb.y*sb.y + vb.z*sb.z + vb.w*sb.w;
        }
        float dh = dA + dB;
        float dot = dh + __shfl_xor_sync(FULL, dh, 16);
        float wg = 0.f, wc = 0.f;
        if (act && half == 0){
            float4 ni = g_ninfo[bN + mc];
            float d = f_n - ni.x;
            float q2 = sqn + ni.z - 2.f*dot;
            wg = 1.f - d*d;
            wc = sqrtf(fmaxf(q2, 0.f) + 1e-12f)*invvol;
            g_wgap[wid*MAXD + j] = wg;
            g_wct [wid*MAXD + j] = wc;
            num_acc += f_n*ni.x + s1n*ni.y;
            sas_acc += dot;
        }
        dg_acc += wg; dc_acc += wc;
        if (half == 0) wgc[eh] = make_float4(wg, wc, __int_as_float(mc), 0.f);
        __syncwarp();
        // both-branch aggregation: broadcast LDS.128 + coalesced LDG, unroll 4
        #pragma unroll 4
        for (int jj = 0; jj < tlen; jj++){
            float4 q = wgc[jj];
            float xv = g_xh[(bN + __float_as_int(q.z))*H + lane];
            y_gap += q.x*xv;
            y_ct  += q.y*xv;
        }
        __syncwarp();
    }
    num_acc = wsum(num_acc);
    sas_acc = wsum(sas_acc);
    float dsum_g = wsum(dg_acc);
    float dsum_c = wsum(dc_acc);

    // lin + pool softmax for both branches (weights from global; L1-hit broadcast)
    float xh = g_xh[wid*H + lane];
    float den_g = 0.f, den_c = 0.f;
    #pragma unroll
    for (int br = 0; br < 2; br++){
        float y = br ? y_ct : y_gap;
        const float* brel = br ? br1 : br0;
        const float* bmc  = br ? bm1 : bm0;
        const float* Wr = br ? Wr1 : Wr0;
        const float* Wo = br ? Wo1 : Wo0;
        const float* Wm = br ? Wm1 : Wm0;
        float acc = brel[lane];
        #pragma unroll
        for (int j = 0; j < 32; j++){
            acc += __shfl_sync(FULL, y,  j) * Wr[j*H + lane];
            acc += __shfl_sync(FULL, xh, j) * Wo[j*H + lane];
        }
        g_xg[br*BN*H + wid*H + lane] = acc;
        float a = (lane < KM) ? bmc[lane] : 0.f;
        #pragma unroll
        for (int j = 0; j < 32; j++){
            float xj = __shfl_sync(FULL, acc, j);
            if (lane < KM) a += xj * Wm[j*KM + lane];
        }
        float mm = a;
        #pragma unroll
        for (int o = 8; o; o >>= 1) mm = fmaxf(mm, __shfl_xor_sync(FULL, mm, o, 16));
        float e = (lane < KM) ? expf(a - mm) : 0.f;
        float es = wsum16(e);
        float s = e/es;
        if (lane < KM) g_smc[br*BN*KM + wid*KM + lane] = s;
        float sq = wsum16(s*s);
        if (br) den_c = sq; else den_g = sq;
    }
    if (lane == 0){
        atomicAdd(&shred[0], num_acc);
        atomicAdd(&shred[1], sas_acc);
        atomicAdd(&shred[2], dsum_g*den_g);
        atomicAdd(&shred[3], dsum_c*den_c);
    }
    __syncthreads();
    if (threadIdx.x < 4){
        int bb = blockIdx.x >> 7;
        const int dst[4] = {ACC_NUMRW, ACC_SAS, ACC_DENP, ACC_DENP + B};
        atomicAdd(&g_acc[dst[threadIdx.x] + bb], shred[threadIdx.x]);
    }
}

// batch-staged pool: one block = (128-node chunk, batch, branch).
// Full batch smc (64KB) staged in DYNAMIC smem; t16 gathers hit shared memory.
__global__ void k_pool(){
    extern __shared__ float smc_s[];       // N*KM = 16384 floats = 64KB
    __shared__ float st16[128*17];
    int c = blockIdx.x, b = blockIdx.y, br = blockIdx.z;
    int t = threadIdx.x;                   // 1024
    int w = t >> 5, lane = t & 31;
    int bN = b*N;
    const float* smc = g_smc + br*BN*KM;
    {
        float4* dst = (float4*)smc_s;
        const float4* src = (const float4*)(smc + bN*KM);
        #pragma unroll
        for (int i = 0; i < 4; i++) dst[t + i*1024] = src[t + i*1024];
    }
    __syncthreads();
    int half = lane >> 4, l16 = lane & 15;
    #pragma unroll
    for (int q = 0; q < 4; q++){
        int nl = c*128 + w*4 + q;          // local node in batch
        int r = bN + nl;
        int deg = g_deg[r];
        const int* cols = g_cols + r*MAXD;
        const float* w_arr = (br ? g_wct : g_wgap) + r*MAXD;
        float tacc = 0.f;
        #pragma unroll 2
        for (int j = half; j < deg; j += 2)
            tacc += w_arr[j] * smc_s[cols[j]*KM + l16];
        tacc += __shfl_down_sync(FULL, tacc, 16);
        if (lane < KM) st16[(w*4+q)*17 + l16] = tacc;
    }
    __syncthreads();
    int base = (br*B + b)*256;
    int n0 = c*128;
    if (t < 256){
        int k = t >> 4, l = t & 15;
        float oa = 0.f;
        #pragma unroll 4
        for (int n = 0; n < 128; n++)
            oa += smc_s[(n0+n)*KM + k] * st16[n*17 + l];
        atomicAdd(&g_acc[ACC_OA + base + t], oa);
    } else if (t < 512){
        int k = (t-256) >> 4, l = t & 15;
        float ssv = 0.f;
        #pragma unroll 4
        for (int n = 0; n < 128; n++)
            ssv += smc_s[(n0+n)*KM + k] * smc_s[(n0+n)*KM + l];
        atomicAdd(&g_acc[ACC_SSP + base + (t-256)], ssv);
    } else {
        int kk = (t-512) >> 5, h = t & 31;
        float px = 0.f;
        const float* xg = g_xg + br*BN*H + (size_t)(bN + n0)*H;
        #pragma unroll 4
        for (int n = 0; n < 128; n++)
            px += smc_s[(n0+n)*KM + kk] * xg[n*H + h];
        atomicAdd(&g_acc[ACC_PX + (br*B + b)*512 + (t-512)], px);
    }
}

// finalize pool: pool losses + normalized pooladj + pooled DGC; br==0 blocks
// additionally compute the CT ortho/ct/rw losses (merged k_ctfin).
__global__ void k_poolfin(const float* __restrict__ W2g_rel, const float* __restrict__ b2g,
                          const float* __restrict__ W2g_root){
    int b = blockIdx.x, br = blockIdx.y, t = threadIdx.x;   // 512
    __shared__ float oa[256], ssm[256], px[512], t2[512], pa[256], red[512], nrm_s;
    int base = (br*B + b)*256;
    if (t < 256){ oa[t] = g_acc[ACC_OA + base + t]; ssm[t] = g_acc[ACC_SSP + base + t]; }
    px[t] = g_acc[ACC_PX + (br*B + b)*512 + t];
    __syncthreads();
    red[t] = (t < 256) ? ssm[t]*ssm[t] : 0.f;
    __syncthreads();
    for (int o = 256; o; o >>= 1){ if (t < o) red[t] += red[t+o]; __syncthreads(); }
    if (t == 0) nrm_s = sqrtf(red[0]);
    __syncthreads();
    if (t < 256){
        int k = t >> 4, l = t & 15;
        float d = ssm[t]/nrm_s - ((k == l) ? 0.25f : 0.f);
        red[t] = d*d;
    } else red[t] = 0.f;
    __syncthreads();
    for (int o = 256; o; o >>= 1){ if (t < o) red[t] += red[t+o]; __syncthreads(); }
    if (t == 0){
        float num = 0.f;
        #pragma unroll
        for (int k = 0; k < KM; k++) num += oa[k*KM + k];
        float den = g_acc[ACC_DENP + br*B + b] + EPSV;
        atomicAdd(&g_acc[ACC_LOSS],   -(num/den)/(float)B);
        atomicAdd(&g_acc[ACC_LOSS+1], sqrtf(red[0])/(float)B);
    }
    __shared__ float dsq[KM];
    if (t < KM){
        float rs = 0.f;
        #pragma unroll
        for (int l = 0; l < KM; l++) rs += (l == t) ? 0.f : oa[t*KM + l];
        dsq[t] = sqrtf(rs) + EPSV;
    }
    __syncthreads();
    if (t < 256){
        int k = t >> 4, l = t & 15;
        pa[t] = (k == l) ? 0.f : oa[t]/(dsq[k]*dsq[l]);
    }
    __syncthreads();
    int k = t >> 5, h = t & 31;
    float a = 0.f;
    #pragma unroll
    for (int l = 0; l < KM; l++) a += pa[k*KM + l]*px[l*H + h];
    t2[t] = a;
    __syncthreads();
    float accv = b2g[h];
    #pragma unroll
    for (int j = 0; j < H; j++)
        accv += t2[k*H + j]*W2g_rel[j*H + h] + px[k*H + j]*W2g_root[j*H + h];
    g_x2[br*B*KM*H + b*KM*H + t] = accv;

    // ---- merged CT/rewiring losses (br==0 blocks only) ----
    if (br == 0){
        __syncthreads();
        float v1 = g_acc[ACC_SSCT + b*1024 + t];
        float v2 = g_acc[ACC_SSCT + b*1024 + t + 512];
        red[t] = v1*v1 + v2*v2;
        __syncthreads();
        for (int o = 256; o; o >>= 1){ if (t < o) red[t] += red[t+o]; __syncthreads(); }
        if (t == 0) nrm_s = sqrtf(red[0]);
        __syncthreads();
        float nrm = nrm_s;
        const float isk32 = 0.17677669529663687f;
        int e1 = t,       k1 = e1 >> 5, l1 = e1 & 31;
        int e2 = t + 512, k2 = e2 >> 5, l2 = e2 & 31;
        float d1 = v1/nrm - ((k1 == l1) ? isk32 : 0.f);
        float d2 = v2/nrm - ((k2 == l2) ? isk32 : 0.f);
        red[t] = d1*d1 + d2*d2;
        __syncthreads();
        for (int o = 256; o; o >>= 1){ if (t < o) red[t] += red[t+o]; __syncthreads(); }
        if (t == 0){
            float sas = g_acc[ACC_SAS + b];
            float den = g_acc[ACC_DENCT + b] + EPSV;
            float sds = g_acc[ACC_SDS + b];
            float lm = ((sds - sas)/den)/(float)B;
            float lo = sqrtf(red[0])/(float)B;
            float num = g_acc[ACC_NUMRW + b];
            float dnr = g_acc[ACC_DENRW + b] + EPSV;
            float s00 = g_acc[ACC_S00 + b];
            float s01 = g_acc[ACC_S01 + b];
            float s11 = g_acc[ACC_S11 + b];
            float nrm2 = sqrtf(s00*s00 + 2.f*s01*s01 + s11*s11);
            const float isk = 0.70710678118654752f;
            float d00 = s00/nrm2 - isk, d01 = s01/nrm2, d11 = s11/nrm2 - isk;
            lm += -(num/dnr)/(float)B;
            lo += sqrtf(d00*d00 + 2.f*d01*d01 + d11*d11)/(float)B;
            atomicAdd(&g_acc[ACC_LOSS],   lm);
            atomicAdd(&g_acc[ACC_LOSS+1], lo);
        }
    }
}

__global__ void k_readout(const float* __restrict__ Wcat, const float* __restrict__ bcat,
                          const float* __restrict__ W2,  const float* __restrict__ b2,
                          const float* __restrict__ W3,  const float* __restrict__ b3,
                          float* __restrict__ out){
    int b = blockIdx.x, h = threadIdx.x;   // 32
    __shared__ float h1[H], h2[H], lg[10];
    float acc = 0.f;
    for (int kk = 0; kk < KM; kk++){
        float z = bcat[h];
        #pragma unroll
        for (int j = 0; j < H; j++) z += g_x2[b*KM*H + kk*H + j]*Wcat[j*H + h];
        #pragma unroll
        for (int j = 0; j < H; j++) z += g_x2[B*KM*H + b*KM*H + kk*H + j]*Wcat[(H+j)*H + h];
        acc += fmaxf(z, 0.f);
    }
    h1[h] = acc; __syncwarp();
    float z2 = b2[h];
    #pragma unroll
    for (int j = 0; j < H; j++) z2 += h1[j]*W2[j*H + h];
    h2[h] = fmaxf(z2, 0.f); __syncwarp();
    if (h < 10){
        float z = b3[h];
        #pragma unroll
        for (int j = 0; j < H; j++) z += h2[j]*W3[j*10 + h];
        lg[h] = z;
    }
    __syncwarp();
    if (h < 10){
        float m = lg[0];
        #pragma unroll
        for (int i = 1; i < 10; i++) m = fmaxf(m, lg[i]);
        float s = 0.f;
        #pragma unroll
        for (int i = 0; i < 10; i++) s += expf(lg[i] - m);
        out[b*10 + h] = lg[h] - m - logf(s);
    }
    if (b == 0 && h == 31){
        out[B*10]     = g_acc[ACC_LOSS];
        out[B*10 + 1] = g_acc[ACC_LOSS+1];
    }
}

extern "C" void kernel_launch(void* const* d_in, const int* in_sizes, int n_in,
                              void* d_out, int out_size){
    const float* x      = (const float*)d_in[0];
    const float* adj    = (const float*)d_in[1];
    const float* W1     = (const float*)d_in[3];
    const float* b1     = (const float*)d_in[4];
    const float* Wrw    = (const float*)d_in[5];
    const float* brw    = (const float*)d_in[6];
    const float* Wg_rel = (const float*)d_in[7];
    const float* bg     = (const float*)d_in[8];
    const float* Wg_root= (const float*)d_in[9];
    const float* Wmcg   = (const float*)d_in[10];
    const float* bmcg   = (const float*)d_in[11];
    const float* W2g_rel= (const float*)d_in[12];
    const float* b2g    = (const float*)d_in[13];
    const float* W2g_root=(const float*)d_in[14];
    const float* Wct    = (const float*)d_in[15];
    const float* bct    = (const float*)d_in[16];
    const float* Wc_rel = (const float*)d_in[17];
    const float* bc     = (const float*)d_in[18];
    const float* Wc_root= (const float*)d_in[19];
    const float* Wmcc   = (const float*)d_in[20];
    const float* bmcc   = (const float*)d_in[21];
    const float* Wcat   = (const float*)d_in[22];
    const float* bcat   = (const float*)d_in[23];
    const float* W2     = (const float*)d_in[24];
    const float* b2     = (const float*)d_in[25];
    const float* W3     = (const float*)d_in[26];
    const float* b3     = (const float*)d_in[27];
    float* out = (float*)d_out;

    cudaFuncSetAttribute(k_pool, cudaFuncAttributeMaxDynamicSharedMemorySize, 65536);

    k_init<<<(ACC_TOTAL+511)/512, 512>>>();
    k_build_soft<<<BN/8, 256>>>(adj, x, W1, b1, Wrw, brw, Wct, bct);
    k_ctpart<<<B*8, 1024>>>();
    k_edgeagg<<<BN/8, 256>>>(Wg_rel, bg, Wg_root, Wmcg, bmcg,
                             Wc_rel, bc, Wc_root, Wmcc, bmcc);
    k_pool<<<dim3(8, B, 2), 1024, 65536>>>();
    k_poolfin<<<dim3(B, 2), 512>>>(W2g_rel, b2g, W2g_root);
    k_readout<<<B, 32>>>(Wcat, bcat, W2, b2, W3, b3, out);

    (void)in_sizes; (void)n_in; (void)out_size;
}

// round 15
// speedup vs baseline: 1.0837x; 1.0202x over previous
#include <cuda_runtime.h>
#include <math.h>
#include <stdint.h>

#define B 16
#define N 1024
#define BN (B*N)
#define IN 128
#define H 32
#define KC 32
#define KM 16
#define MAXD 128
#define EPSV 1e-15f
#define FULL 0xffffffffu

// ---------------- accumulator slab (atomically accumulated; zeroed per run) --
#define ACC_NUMRW 0                    // [B]
#define ACC_DENRW 16                   // [B]
#define ACC_S00   32                   // [B]
#define ACC_S01   48                   // [B]
#define ACC_S11   64                   // [B]
#define ACC_SAS   80                   // [B]
#define ACC_DENCT 96                   // [B]
#define ACC_SDS   112                  // [B]
#define ACC_VOL   128                  // [B]
#define ACC_SSCT  144                  // [B][32*32]
#define ACC_OA    (ACC_SSCT+B*1024)    // [2][B][256]
#define ACC_SSP   (ACC_OA+2*B*256)     // [2][B][256]
#define ACC_PX    (ACC_SSP+2*B*256)    // [2][B][512]
#define ACC_DENP  (ACC_PX+2*B*512)     // [2][B]
#define ACC_LOSS  (ACC_DENP+2*B)       // [2] main, ortho
#define ACC_TOTAL (ACC_LOSS+2)

__device__ float g_acc[ACC_TOTAL];

// ---------------- scratch ----------------------------------------------------
__device__ float g_xh[BN*H];
__device__ int   g_cols[BN*MAXD];
__device__ int   g_deg[BN];
__device__ float g_srw[BN*2];
__device__ float4 g_ninfo[BN];        // {srw0, srw1, sqct, 0} packed per node
__device__ float g_sct[BN*KC];
__device__ float g_sqct[BN];
__device__ float g_wgap[BN*MAXD];
__device__ float g_wct[BN*MAXD];
__device__ float g_xg[2*BN*H];
__device__ float g_smc[2*BN*KM];
__device__ float g_x2[2*B*KM*H];

__device__ __forceinline__ float wsum(float v){
    #pragma unroll
    for(int o=16;o;o>>=1) v += __shfl_xor_sync(FULL, v, o);
    return v;
}
__device__ __forceinline__ float wsum16(float v){
    #pragma unroll
    for(int o=8;o;o>>=1) v += __shfl_xor_sync(FULL, v, o, 16);
    return v;
}

__global__ void k_init(){
    int i = blockIdx.x*blockDim.x + threadIdx.x;
    if (i < ACC_TOTAL) g_acc[i] = 0.f;
}

// fused: neighbor lists (prefetched float4 + ballot compaction, MLP=8) + vol +
//        xh=x@W1+b1 + rewiring softmax(k=2) + CT softmax(k=32) + scalar partials
__global__ void k_build_soft(const float* __restrict__ adj, const float* __restrict__ x,
                             const float* __restrict__ W1,  const float* __restrict__ b1,
                             const float* __restrict__ Wrw, const float* __restrict__ brw,
                             const float* __restrict__ Wct, const float* __restrict__ bct){
    __shared__ float W1s[IN*H];      // 16 KB
    __shared__ float Wcts[H*KC];     // 4 KB
    __shared__ float svol[8];
    __shared__ float sh[6];
    for (int i = threadIdx.x; i < IN*H; i += blockDim.x) W1s[i] = W1[i];
    for (int i = threadIdx.x; i < H*KC; i += blockDim.x) Wcts[i] = Wct[i];
    if (threadIdx.x < 6) sh[threadIdx.x] = 0.f;
    __syncthreads();

    int wid = (blockIdx.x*blockDim.x + threadIdx.x) >> 5;
    int lane = threadIdx.x & 31;
    int wz = threadIdx.x >> 5;

    // ---- neighbor list: prefetch entire row (MLP=8), then compact ----
    const float4* row = (const float4*)(adj + (size_t)wid * N);
    int* cols = g_cols + (size_t)wid * MAXD;
    float4 v[8];
    #pragma unroll
    for (int i = 0; i < 8; i++) v[i] = row[i*32 + lane];
    int cnt = 0;
    #pragma unroll
    for (int i = 0; i < 8; i++){
        bool n0=v[i].x!=0.f, n1=v[i].y!=0.f, n2=v[i].z!=0.f, n3=v[i].w!=0.f;
        unsigned m0=__ballot_sync(FULL,n0), m1=__ballot_sync(FULL,n1);
        unsigned m2=__ballot_sync(FULL,n2), m3=__ballot_sync(FULL,n3);
        unsigned below = (1u<<lane) - 1u;
        int idx = cnt + __popc(m0&below)+__popc(m1&below)+__popc(m2&below)+__popc(m3&below);
        int col0 = i*128 + lane*4;
        if(n0 && idx<MAXD){ cols[idx]=col0;   idx++; }
        if(n1 && idx<MAXD){ cols[idx]=col0+1; idx++; }
        if(n2 && idx<MAXD){ cols[idx]=col0+2; idx++; }
        if(n3 && idx<MAXD){ cols[idx]=col0+3; idx++; }
        cnt += __popc(m0)+__popc(m1)+__popc(m2)+__popc(m3);
    }
    int deg = cnt < MAXD ? cnt : MAXD;
    if (lane == 0){ g_deg[wid] = deg; svol[wz] = (float)deg; }

    // ---- xh = x @ W1 + b1 (lane = h) ----
    float acc = b1[lane];
    const float* xr = x + (size_t)wid*IN;
    #pragma unroll
    for (int c = 0; c < 4; c++){
        float xv = xr[c*32 + lane];
        #pragma unroll
        for (int j = 0; j < 32; j++)
            acc += __shfl_sync(FULL, xv, j) * W1s[(c*32+j)*H + lane];
    }
    g_xh[wid*H + lane] = acc;

    // ---- rewiring softmax (k=2) ----
    float a0 = wsum(acc*Wrw[lane*2])   + brw[0];
    float a1 = wsum(acc*Wrw[lane*2+1]) + brw[1];
    float mm = fmaxf(a0,a1);
    float e0 = expf(a0-mm), e1 = expf(a1-mm);
    float inv = 1.f/(e0+e1);
    float s0 = e0*inv, s1 = e1*inv;
    if (lane == 0){ g_srw[2*wid]=s0; g_srw[2*wid+1]=s1; }

    // ---- CT softmax (k=32, lane = k) ----
    float a = bct[lane];
    #pragma unroll
    for (int j = 0; j < 32; j++)
        a += __shfl_sync(FULL, acc, j) * Wcts[j*KC + lane];
    float m = a;
    #pragma unroll
    for (int o = 16; o; o >>= 1) m = fmaxf(m, __shfl_xor_sync(FULL, m, o));
    float e = expf(a - m);
    float s = e / wsum(e);
    g_sct[wid*KC + lane] = s;
    float sq = wsum(s*s);
    if (lane == 0){
        g_sqct[wid] = sq;
        g_ninfo[wid] = make_float4(s0, s1, sq, 0.f);
    }

    // ---- per-batch scalar partials ----
    if (lane == 0){
        atomicAdd(&sh[0], (float)deg*(s0*s0 + s1*s1)); // den_rw
        atomicAdd(&sh[1], s0*s0);                      // s00
        atomicAdd(&sh[2], s0*s1);                      // s01
        atomicAdd(&sh[3], s1*s1);                      // s11
        atomicAdd(&sh[4], sq);                         // den_ct
        atomicAdd(&sh[5], (float)deg*sq);              // sds
    }
    __syncthreads();
    int b = blockIdx.x >> 7;
    if (threadIdx.x < 6){
        const int dst[6] = {ACC_DENRW, ACC_S00, ACC_S01, ACC_S11, ACC_DENCT, ACC_SDS};
        atomicAdd(&g_acc[dst[threadIdx.x] + b], sh[threadIdx.x]);
    }
    if (threadIdx.x == 0){
        float vs = 0.f;
        #pragma unroll
        for (int i = 0; i < 8; i++) vs += svol[i];
        atomicAdd(&g_acc[ACC_VOL + b], vs);
    }
}

// S^T S partials from smem tiles (128-node chunks)
__global__ void k_ctpart(){
    int b = blockIdx.x >> 3, c = blockIdx.x & 7;
    int t = threadIdx.x;   // 1024
    __shared__ float S[128][33];
    int n0 = (b*N + c*128)*KC;
    #pragma unroll
    for (int i = 0; i < 4; i++){
        int idx = t + i*1024;
        S[idx>>5][idx&31] = g_sct[n0 + idx];
    }
    __syncthreads();
    int k = t >> 5, l = t & 31;
    float ssv = 0.f;
    #pragma unroll 8
    for (int n = 0; n < 128; n++)
        ssv += S[n][k]*S[n][l];
    atomicAdd(&g_acc[ACC_SSCT + b*1024 + t], ssv);
}

// MEGA-FUSED edge kernel: dot fused into the row load (no staging buffer).
// Per 16-edge tile: prefetch 4 row-slices (MLP=4), FMA vs register sn slice,
// 4 independent 3-shfl segment reductions; tiny smem for dots + weights.
__global__ void __launch_bounds__(256, 5)
k_edgeagg(const float* __restrict__ Wr0, const float* __restrict__ br0,
          const float* __restrict__ Wo0, const float* __restrict__ Wm0,
          const float* __restrict__ bm0,
          const float* __restrict__ Wr1, const float* __restrict__ br1,
          const float* __restrict__ Wo1, const float* __restrict__ Wm1,
          const float* __restrict__ bm1){
    __shared__ float4 SN[8][8];                     // sn per warp (32 floats)
    __shared__ float  SD[8][16];                    // per-edge dots
    __shared__ float4 WGC[8][16];                   // {wg, wc, mc, 0} per edge
    __shared__ float shred[4];                      // num, sas, denp0, denp1
    if (threadIdx.x < 4) shred[threadIdx.x] = 0.f;
    __syncthreads();

    int wid = (blockIdx.x*blockDim.x + threadIdx.x) >> 5;
    int lane = threadIdx.x & 31;
    int w = threadIdx.x >> 5;
    float4* wgc = WGC[w];
    int b = wid >> 10, bN = b << 10;
    int deg = g_deg[wid];
    const int* cols = g_cols + wid*MAXD;
    float f_n = g_srw[2*wid];
    float s1n = g_srw[2*wid+1];
    float sn  = g_sct[wid*KC + lane];
    float sqn = g_sqct[wid];
    float invvol = 1.f/(g_acc[ACC_VOL + b] + EPSV);
    float num_acc = 0.f, sas_acc = 0.f;
    float dg_acc = 0.f, dc_acc = 0.f;
    float y_gap = 0.f, y_ct = 0.f;         // lane = h

    // stage sn into smem once; each lane keeps its float4 slice in a register
    ((float*)SN[w])[lane] = sn;
    __syncwarp();
    int r8 = lane >> 3;        // 0..3 : row within 4-row group
    int p8 = lane & 7;         // 0..7 : float4 slot of the row
    float4 snr = SN[w][p8];    // register-resident sn slice (loop-invariant)
    int eh = lane & 15;        // edge within subtile
    int half = lane >> 4;

    for (int j0 = 0; j0 < deg; j0 += 16){
        int tlen = deg - j0; if (tlen > 16) tlen = 16;
        int jl = j0 + lane;
        int mycol = -1;
        if (jl < deg) mycol = cols[jl];
        // prefetch 4 row-slices (one per g), MLP=4
        float4 v[4];
        int mcg[4];
        #pragma unroll
        for (int g = 0; g < 4; g++){
            int e = g*4 + r8;
            int mc = __shfl_sync(FULL, mycol, e);
            mcg[g] = mc;
            if (mc >= 0) v[g] = ((const float4*)(g_sct + (size_t)(bN+mc)*KC))[p8];
            else         v[g] = make_float4(0.f,0.f,0.f,0.f);
        }
        // 4 independent segment-reduced dots (8 consecutive lanes per row)
        #pragma unroll
        for (int g = 0; g < 4; g++){
            float pd = v[g].x*snr.x + v[g].y*snr.y + v[g].z*snr.z + v[g].w*snr.w;
            pd += __shfl_xor_sync(FULL, pd, 1);
            pd += __shfl_xor_sync(FULL, pd, 2);
            pd += __shfl_xor_sync(FULL, pd, 4);
            if (p8 == 0) SD[w][g*4 + r8] = pd;
        }
        __syncwarp();
        // per-edge weights on lanes 0..15
        int j = j0 + eh;
        bool act = (j < deg) && (half == 0);
        float wg = 0.f, wc = 0.f;
        int mc16 = __shfl_sync(FULL, mycol, eh);
        if (act){
            float dot = SD[w][eh];
            float4 ni = g_ninfo[bN + mc16];
            float d = f_n - ni.x;
            float q2 = sqn + ni.z - 2.f*dot;
            wg = 1.f - d*d;
            wc = sqrtf(fmaxf(q2, 0.f) + 1e-12f)*invvol;
            g_wgap[wid*MAXD + j] = wg;
            g_wct [wid*MAXD + j] = wc;
            num_acc += f_n*ni.x + s1n*ni.y;
            sas_acc += dot;
            dg_acc += wg; dc_acc += wc;
        }
        if (half == 0) wgc[eh] = make_float4(wg, wc, __int_as_float(mc16 < 0 ? 0 : mc16), 0.f);
        __syncwarp();
        // both-branch aggregation: broadcast LDS.128 + coalesced LDG, unroll 4
        #pragma unroll 4
        for (int jj = 0; jj < tlen; jj++){
            float4 q = wgc[jj];
            float xv = g_xh[(bN + __float_as_int(q.z))*H + lane];
            y_gap += q.x*xv;
            y_ct  += q.y*xv;
        }
        __syncwarp();
    }
    num_acc = wsum(num_acc);
    sas_acc = wsum(sas_acc);
    float dsum_g = wsum(dg_acc);
    float dsum_c = wsum(dc_acc);

    // lin + pool softmax for both branches (weights from global; L1-hit broadcast)
    float xh = g_xh[wid*H + lane];
    float den_g = 0.f, den_c = 0.f;
    #pragma unroll
    for (int br = 0; br < 2; br++){
        float y = br ? y_ct : y_gap;
        const float* brel = br ? br1 : br0;
        const float* bmc  = br ? bm1 : bm0;
        const float* Wr = br ? Wr1 : Wr0;
        const float* Wo = br ? Wo1 : Wo0;
        const float* Wm = br ? Wm1 : Wm0;
        float acc = brel[lane];
        #pragma unroll
        for (int j = 0; j < 32; j++){
            acc += __shfl_sync(FULL, y,  j) * Wr[j*H + lane];
            acc += __shfl_sync(FULL, xh, j) * Wo[j*H + lane];
        }
        g_xg[br*BN*H + wid*H + lane] = acc;
        float a = (lane < KM) ? bmc[lane] : 0.f;
        #pragma unroll
        for (int j = 0; j < 32; j++){
            float xj = __shfl_sync(FULL, acc, j);
            if (lane < KM) a += xj * Wm[j*KM + lane];
        }
        float mm = a;
        #pragma unroll
        for (int o = 8; o; o >>= 1) mm = fmaxf(mm, __shfl_xor_sync(FULL, mm, o, 16));
        float e = (lane < KM) ? expf(a - mm) : 0.f;
        float es = wsum16(e);
        float s = e/es;
        if (lane < KM) g_smc[br*BN*KM + wid*KM + lane] = s;
        float sq = wsum16(s*s);
        if (br) den_c = sq; else den_g = sq;
    }
    if (lane == 0){
        atomicAdd(&shred[0], num_acc);
        atomicAdd(&shred[1], sas_acc);
        atomicAdd(&shred[2], dsum_g*den_g);
        atomicAdd(&shred[3], dsum_c*den_c);
    }
    __syncthreads();
    if (threadIdx.x < 4){
        int bb = blockIdx.x >> 7;
        const int dst[4] = {ACC_NUMRW, ACC_SAS, ACC_DENP, ACC_DENP + B};
        atomicAdd(&g_acc[dst[threadIdx.x] + bb], shred[threadIdx.x]);
    }
}

// batch-staged pool: one block = (128-node chunk, batch, branch).
// Full batch smc (64KB) staged in DYNAMIC smem; t16 gathers hit shared memory.
__global__ void k_pool(){
    extern __shared__ float smc_s[];       // N*KM = 16384 floats = 64KB
    __shared__ float st16[128*17];
    int c = blockIdx.x, b = blockIdx.y, br = blockIdx.z;
    int t = threadIdx.x;                   // 1024
    int w = t >> 5, lane = t & 31;
    int bN = b*N;
    const float* smc = g_smc + br*BN*KM;
    {
        float4* dst = (float4*)smc_s;
        const float4* src = (const float4*)(smc + bN*KM);
        #pragma unroll
        for (int i = 0; i < 4; i++) dst[t + i*1024] = src[t + i*1024];
    }
    __syncthreads();
    int half = lane >> 4, l16 = lane & 15;
    #pragma unroll
    for (int q = 0; q < 4; q++){
        int nl = c*128 + w*4 + q;          // local node in batch
        int r = bN + nl;
        int deg = g_deg[r];
        const int* cols = g_cols + r*MAXD;
        const float* w_arr = (br ? g_wct : g_wgap) + r*MAXD;
        float tacc = 0.f;
        #pragma unroll 2
        for (int j = half; j < deg; j += 2)
            tacc += w_arr[j] * smc_s[cols[j]*KM + l16];
        tacc += __shfl_down_sync(FULL, tacc, 16);
        if (lane < KM) st16[(w*4+q)*17 + l16] = tacc;
    }
    __syncthreads();
    int base = (br*B + b)*256;
    int n0 = c*128;
    if (t < 256){
        int k = t >> 4, l = t & 15;
        float oa = 0.f;
        #pragma unroll 4
        for (int n = 0; n < 128; n++)
            oa += smc_s[(n0+n)*KM + k] * st16[n*17 + l];
        atomicAdd(&g_acc[ACC_OA + base + t], oa);
    } else if (t < 512){
        int k = (t-256) >> 4, l = t & 15;
        float ssv = 0.f;
        #pragma unroll 4
        for (int n = 0; n < 128; n++)
            ssv += smc_s[(n0+n)*KM + k] * smc_s[(n0+n)*KM + l];
        atomicAdd(&g_acc[ACC_SSP + base + (t-256)], ssv);
    } else {
        int kk = (t-512) >> 5, h = t & 31;
        float px = 0.f;
        const float* xg = g_xg + br*BN*H + (size_t)(bN + n0)*H;
        #pragma unroll 4
        for (int n = 0; n < 128; n++)
            px += smc_s[(n0+n)*KM + kk] * xg[n*H + h];
        atomicAdd(&g_acc[ACC_PX + (br*B + b)*512 + (t-512)], px);
    }
}

// finalize pool: pool losses + normalized pooladj + pooled DGC; br==0 blocks
// additionally compute the CT ortho/ct/rw losses (merged k_ctfin).
__global__ void k_poolfin(const float* __restrict__ W2g_rel, const float* __restrict__ b2g,
                          const float* __restrict__ W2g_root){
    int b = blockIdx.x, br = blockIdx.y, t = threadIdx.x;   // 512
    __shared__ float oa[256], ssm[256], px[512], t2[512], pa[256], red[512], nrm_s;
    int base = (br*B + b)*256;
    if (t < 256){ oa[t] = g_acc[ACC_OA + base + t]; ssm[t] = g_acc[ACC_SSP + base + t]; }
    px[t] = g_acc[ACC_PX + (br*B + b)*512 + t];
    __syncthreads();
    red[t] = (t < 256) ? ssm[t]*ssm[t] : 0.f;
    __syncthreads();
    for (int o = 256; o; o >>= 1){ if (t < o) red[t] += red[t+o]; __syncthreads(); }
    if (t == 0) nrm_s = sqrtf(red[0]);
    __syncthreads();
    if (t < 256){
        int k = t >> 4, l = t & 15;
        float d = ssm[t]/nrm_s - ((k == l) ? 0.25f : 0.f);
        red[t] = d*d;
    } else red[t] = 0.f;
    __syncthreads();
    for (int o = 256; o; o >>= 1){ if (t < o) red[t] += red[t+o]; __syncthreads(); }
    if (t == 0){
        float num = 0.f;
        #pragma unroll
        for (int k = 0; k < KM; k++) num += oa[k*KM + k];
        float den = g_acc[ACC_DENP + br*B + b] + EPSV;
        atomicAdd(&g_acc[ACC_LOSS],   -(num/den)/(float)B);
        atomicAdd(&g_acc[ACC_LOSS+1], sqrtf(red[0])/(float)B);
    }
    __shared__ float dsq[KM];
    if (t < KM){
        float rs = 0.f;
        #pragma unroll
        for (int l = 0; l < KM; l++) rs += (l == t) ? 0.f : oa[t*KM + l];
        dsq[t] = sqrtf(rs) + EPSV;
    }
    __syncthreads();
    if (t < 256){
        int k = t >> 4, l = t & 15;
        pa[t] = (k == l) ? 0.f : oa[t]/(dsq[k]*dsq[l]);
    }
    __syncthreads();
    int k = t >> 5, h = t & 31;
    float a = 0.f;
    #pragma unroll
    for (int l = 0; l < KM; l++) a += pa[k*KM + l]*px[l*H + h];
    t2[t] = a;
    __syncthreads();
    float accv = b2g[h];
    #pragma unroll
    for (int j = 0; j < H; j++)
        accv += t2[k*H + j]*W2g_rel[j*H + h] + px[k*H + j]*W2g_root[j*H + h];
    g_x2[br*B*KM*H + b*KM*H + t] = accv;

    // ---- merged CT/rewiring losses (br==0 blocks only) ----
    if (br == 0){
        __syncthreads();
        float v1 = g_acc[ACC_SSCT + b*1024 + t];
        float v2 = g_acc[ACC_SSCT + b*1024 + t + 512];
        red[t] = v1*v1 + v2*v2;
        __syncthreads();
        for (int o = 256; o; o >>= 1){ if (t < o) red[t] += red[t+o]; __syncthreads(); }
        if (t == 0) nrm_s = sqrtf(red[0]);
        __syncthreads();
        float nrm = nrm_s;
        const float isk32 = 0.17677669529663687f;
        int e1 = t,       k1 = e1 >> 5, l1 = e1 & 31;
        int e2 = t + 512, k2 = e2 >> 5, l2 = e2 & 31;
        float d1 = v1/nrm - ((k1 == l1) ? isk32 : 0.f);
        float d2 = v2/nrm - ((k2 == l2) ? isk32 : 0.f);
        red[t] = d1*d1 + d2*d2;
        __syncthreads();
        for (int o = 256; o; o >>= 1){ if (t < o) red[t] += red[t+o]; __syncthreads(); }
        if (t == 0){
            float sas = g_acc[ACC_SAS + b];
            float den = g_acc[ACC_DENCT + b] + EPSV;
            float sds = g_acc[ACC_SDS + b];
            float lm = ((sds - sas)/den)/(float)B;
            float lo = sqrtf(red[0])/(float)B;
            float num = g_acc[ACC_NUMRW + b];
            float dnr = g_acc[ACC_DENRW + b] + EPSV;
            float s00 = g_acc[ACC_S00 + b];
            float s01 = g_acc[ACC_S01 + b];
            float s11 = g_acc[ACC_S11 + b];
            float nrm2 = sqrtf(s00*s00 + 2.f*s01*s01 + s11*s11);
            const float isk = 0.70710678118654752f;
            float d00 = s00/nrm2 - isk, d01 = s01/nrm2, d11 = s11/nrm2 - isk;
            lm += -(num/dnr)/(float)B;
            lo += sqrtf(d00*d00 + 2.f*d01*d01 + d11*d11)/(float)B;
            atomicAdd(&g_acc[ACC_LOSS],   lm);
            atomicAdd(&g_acc[ACC_LOSS+1], lo);
        }
    }
}

__global__ void k_readout(const float* __restrict__ Wcat, const float* __restrict__ bcat,
                          const float* __restrict__ W2,  const float* __restrict__ b2,
                          const float* __restrict__ W3,  const float* __restrict__ b3,
                          float* __restrict__ out){
    int b = blockIdx.x, h = threadIdx.x;   // 32
    __shared__ float h1[H], h2[H], lg[10];
    float acc = 0.f;
    for (int kk = 0; kk < KM; kk++){
        float z = bcat[h];
        #pragma unroll
        for (int j = 0; j < H; j++) z += g_x2[b*KM*H + kk*H + j]*Wcat[j*H + h];
        #pragma unroll
        for (int j = 0; j < H; j++) z += g_x2[B*KM*H + b*KM*H + kk*H + j]*Wcat[(H+j)*H + h];
        acc += fmaxf(z, 0.f);
    }
    h1[h] = acc; __syncwarp();
    float z2 = b2[h];
    #pragma unroll
    for (int j = 0; j < H; j++) z2 += h1[j]*W2[j*H + h];
    h2[h] = fmaxf(z2, 0.f); __syncwarp();
    if (h < 10){
        float z = b3[h];
        #pragma unroll
        for (int j = 0; j < H; j++) z += h2[j]*W3[j*10 + h];
        lg[h] = z;
    }
    __syncwarp();
    if (h < 10){
        float m = lg[0];
        #pragma unroll
        for (int i = 1; i < 10; i++) m = fmaxf(m, lg[i]);
        float s = 0.f;
        #pragma unroll
        for (int i = 0; i < 10; i++) s += expf(lg[i] - m);
        out[b*10 + h] = lg[h] - m - logf(s);
    }
    if (b == 0 && h == 31){
        out[B*10]     = g_acc[ACC_LOSS];
        out[B*10 + 1] = g_acc[ACC_LOSS+1];
    }
}

extern "C" void kernel_launch(void* const* d_in, const int* in_sizes, int n_in,
                              void* d_out, int out_size){
    const float* x      = (const float*)d_in[0];
    const float* adj    = (const float*)d_in[1];
    const float* W1     = (const float*)d_in[3];
    const float* b1     = (const float*)d_in[4];
    const float* Wrw    = (const float*)d_in[5];
    const float* brw    = (const float*)d_in[6];
    const float* Wg_rel = (const float*)d_in[7];
    const float* bg     = (const float*)d_in[8];
    const float* Wg_root= (const float*)d_in[9];
    const float* Wmcg   = (const float*)d_in[10];
    const float* bmcg   = (const float*)d_in[11];
    const float* W2g_rel= (const float*)d_in[12];
    const float* b2g    = (const float*)d_in[13];
    const float* W2g_root=(const float*)d_in[14];
    const float* Wct    = (const float*)d_in[15];
    const float* bct    = (const float*)d_in[16];
    const float* Wc_rel = (const float*)d_in[17];
    const float* bc     = (const float*)d_in[18];
    const float* Wc_root= (const float*)d_in[19];
    const float* Wmcc   = (const float*)d_in[20];
    const float* bmcc   = (const float*)d_in[21];
    const float* Wcat   = (const float*)d_in[22];
    const float* bcat   = (const float*)d_in[23];
    const float* W2     = (const float*)d_in[24];
    const float* b2     = (const float*)d_in[25];
    const float* W3     = (const float*)d_in[26];
    const float* b3     = (const float*)d_in[27];
    float* out = (float*)d_out;

    cudaFuncSetAttribute(k_pool, cudaFuncAttributeMaxDynamicSharedMemorySize, 65536);

    k_init<<<(ACC_TOTAL+511)/512, 512>>>();
    k_build_soft<<<BN/8, 256>>>(adj, x, W1, b1, Wrw, brw, Wct, bct);
    k_ctpart<<<B*8, 1024>>>();
    k_edgeagg<<<BN/8, 256>>>(Wg_rel, bg, Wg_root, Wmcg, bmcg,
                             Wc_rel, bc, Wc_root, Wmcc, bmcc);
    k_pool<<<dim3(8, B, 2), 1024, 65536>>>();
    k_poolfin<<<dim3(B, 2), 512>>>(W2g_rel, b2g, W2g_root);
    k_readout<<<B, 32>>>(Wcat, bcat, W2, b2, W3, b3, out);

    (void)in_sizes; (void)n_in; (void)out_size;
}

// round 16
// speedup vs baseline: 1.1041x; 1.0188x over previous
#include <cuda_runtime.h>
#include <math.h>
#include <stdint.h>

#define B 16
#define N 1024
#define BN (B*N)
#define IN 128
#define H 32
#define KC 32
#define KM 16
#define MAXD 128
#define EPSV 1e-15f
#define FULL 0xffffffffu

// ---------------- accumulator slab (atomically accumulated; zeroed per run) --
#define ACC_NUMRW 0                    // [B]
#define ACC_DENRW 16                   // [B]
#define ACC_S00   32                   // [B]
#define ACC_S01   48                   // [B]
#define ACC_S11   64                   // [B]
#define ACC_SAS   80                   // [B]
#define ACC_DENCT 96                   // [B]
#define ACC_SDS   112                  // [B]
#define ACC_VOL   128                  // [B]
#define ACC_SSCT  144                  // [B][32*32]
#define ACC_OA    (ACC_SSCT+B*1024)    // [2][B][256]
#define ACC_SSP   (ACC_OA+2*B*256)     // [2][B][256]
#define ACC_PX    (ACC_SSP+2*B*256)    // [2][B][512]
#define ACC_DENP  (ACC_PX+2*B*512)     // [2][B]
#define ACC_LOSS  (ACC_DENP+2*B)       // [2] main, ortho
#define ACC_TOTAL (ACC_LOSS+2)

__device__ float g_acc[ACC_TOTAL];

// ---------------- scratch ----------------------------------------------------
__device__ float g_xh[BN*H];
__device__ int   g_cols[BN*MAXD];
__device__ int   g_deg[BN];
__device__ float g_srw[BN*2];
__device__ float4 g_ninfo[BN];        // {srw0, srw1, sqct, 0} packed per node
__device__ float g_sct[BN*KC];
__device__ float g_sqct[BN];
__device__ float g_wgap[BN*MAXD];
__device__ float g_wct[BN*MAXD];
__device__ float g_xg[2*BN*H];
__device__ float g_smc[2*BN*KM];
__device__ float g_x2[2*B*KM*H];

__device__ __forceinline__ float wsum(float v){
    #pragma unroll
    for(int o=16;o;o>>=1) v += __shfl_xor_sync(FULL, v, o);
    return v;
}
__device__ __forceinline__ float wsum16(float v){
    #pragma unroll
    for(int o=8;o;o>>=1) v += __shfl_xor_sync(FULL, v, o, 16);
    return v;
}

__global__ void k_init(){
    int i = blockIdx.x*blockDim.x + threadIdx.x;
    if (i < ACC_TOTAL) g_acc[i] = 0.f;
}

// fused: neighbor lists (prefetched float4 + ballot compaction, MLP=8) + vol +
//        xh=x@W1+b1 + rewiring softmax(k=2) + CT softmax(k=32) + scalar partials
__global__ void k_build_soft(const float* __restrict__ adj, const float* __restrict__ x,
                             const float* __restrict__ W1,  const float* __restrict__ b1,
                             const float* __restrict__ Wrw, const float* __restrict__ brw,
                             const float* __restrict__ Wct, const float* __restrict__ bct){
    __shared__ float W1s[IN*H];      // 16 KB
    __shared__ float Wcts[H*KC];     // 4 KB
    __shared__ float svol[8];
    __shared__ float sh[6];
    for (int i = threadIdx.x; i < IN*H; i += blockDim.x) W1s[i] = W1[i];
    for (int i = threadIdx.x; i < H*KC; i += blockDim.x) Wcts[i] = Wct[i];
    if (threadIdx.x < 6) sh[threadIdx.x] = 0.f;
    __syncthreads();

    int wid = (blockIdx.x*blockDim.x + threadIdx.x) >> 5;
    int lane = threadIdx.x & 31;
    int wz = threadIdx.x >> 5;

    // ---- neighbor list: prefetch entire row (MLP=8), then compact ----
    const float4* row = (const float4*)(adj + (size_t)wid * N);
    int* cols = g_cols + (size_t)wid * MAXD;
    float4 v[8];
    #pragma unroll
    for (int i = 0; i < 8; i++) v[i] = row[i*32 + lane];
    int cnt = 0;
    #pragma unroll
    for (int i = 0; i < 8; i++){
        bool n0=v[i].x!=0.f, n1=v[i].y!=0.f, n2=v[i].z!=0.f, n3=v[i].w!=0.f;
        unsigned m0=__ballot_sync(FULL,n0), m1=__ballot_sync(FULL,n1);
        unsigned m2=__ballot_sync(FULL,n2), m3=__ballot_sync(FULL,n3);
        unsigned below = (1u<<lane) - 1u;
        int idx = cnt + __popc(m0&below)+__popc(m1&below)+__popc(m2&below)+__popc(m3&below);
        int col0 = i*128 + lane*4;
        if(n0 && idx<MAXD){ cols[idx]=col0;   idx++; }
        if(n1 && idx<MAXD){ cols[idx]=col0+1; idx++; }
        if(n2 && idx<MAXD){ cols[idx]=col0+2; idx++; }
        if(n3 && idx<MAXD){ cols[idx]=col0+3; idx++; }
        cnt += __popc(m0)+__popc(m1)+__popc(m2)+__popc(m3);
    }
    int deg = cnt < MAXD ? cnt : MAXD;
    if (lane == 0){ g_deg[wid] = deg; svol[wz] = (float)deg; }

    // ---- xh = x @ W1 + b1 (lane = h) ----
    float acc = b1[lane];
    const float* xr = x + (size_t)wid*IN;
    #pragma unroll
    for (int c = 0; c < 4; c++){
        float xv = xr[c*32 + lane];
        #pragma unroll
        for (int j = 0; j < 32; j++)
            acc += __shfl_sync(FULL, xv, j) * W1s[(c*32+j)*H + lane];
    }
    g_xh[wid*H + lane] = acc;

    // ---- rewiring softmax (k=2) ----
    float a0 = wsum(acc*Wrw[lane*2])   + brw[0];
    float a1 = wsum(acc*Wrw[lane*2+1]) + brw[1];
    float mm = fmaxf(a0,a1);
    float e0 = expf(a0-mm), e1 = expf(a1-mm);
    float inv = 1.f/(e0+e1);
    float s0 = e0*inv, s1 = e1*inv;
    if (lane == 0){ g_srw[2*wid]=s0; g_srw[2*wid+1]=s1; }

    // ---- CT softmax (k=32, lane = k) ----
    float a = bct[lane];
    #pragma unroll
    for (int j = 0; j < 32; j++)
        a += __shfl_sync(FULL, acc, j) * Wcts[j*KC + lane];
    float m = a;
    #pragma unroll
    for (int o = 16; o; o >>= 1) m = fmaxf(m, __shfl_xor_sync(FULL, m, o));
    float e = expf(a - m);
    float s = e / wsum(e);
    g_sct[wid*KC + lane] = s;
    float sq = wsum(s*s);
    if (lane == 0){
        g_sqct[wid] = sq;
        g_ninfo[wid] = make_float4(s0, s1, sq, 0.f);
    }

    // ---- per-batch scalar partials ----
    if (lane == 0){
        atomicAdd(&sh[0], (float)deg*(s0*s0 + s1*s1)); // den_rw
        atomicAdd(&sh[1], s0*s0);                      // s00
        atomicAdd(&sh[2], s0*s1);                      // s01
        atomicAdd(&sh[3], s1*s1);                      // s11
        atomicAdd(&sh[4], sq);                         // den_ct
        atomicAdd(&sh[5], (float)deg*sq);              // sds
    }
    __syncthreads();
    int b = blockIdx.x >> 7;
    if (threadIdx.x < 6){
        const int dst[6] = {ACC_DENRW, ACC_S00, ACC_S01, ACC_S11, ACC_DENCT, ACC_SDS};
        atomicAdd(&g_acc[dst[threadIdx.x] + b], sh[threadIdx.x]);
    }
    if (threadIdx.x == 0){
        float vs = 0.f;
        #pragma unroll
        for (int i = 0; i < 8; i++) vs += svol[i];
        atomicAdd(&g_acc[ACC_VOL + b], vs);
    }
}

// S^T S partials from smem tiles (128-node chunks)
__global__ void k_ctpart(){
    int b = blockIdx.x >> 3, c = blockIdx.x & 7;
    int t = threadIdx.x;   // 1024
    __shared__ float S[128][33];
    int n0 = (b*N + c*128)*KC;
    #pragma unroll
    for (int i = 0; i < 4; i++){
        int idx = t + i*1024;
        S[idx>>5][idx&31] = g_sct[n0 + idx];
    }
    __syncthreads();
    int k = t >> 5, l = t & 31;
    float ssv = 0.f;
    #pragma unroll 8
    for (int n = 0; n < 128; n++)
        ssv += S[n][k]*S[n][l];
    atomicAdd(&g_acc[ACC_SSCT + b*1024 + t], ssv);
}

// MEGA-FUSED edge kernel: dot fused into the row load (no staging buffer).
__global__ void __launch_bounds__(256, 5)
k_edgeagg(const float* __restrict__ Wr0, const float* __restrict__ br0,
          const float* __restrict__ Wo0, const float* __restrict__ Wm0,
          const float* __restrict__ bm0,
          const float* __restrict__ Wr1, const float* __restrict__ br1,
          const float* __restrict__ Wo1, const float* __restrict__ Wm1,
          const float* __restrict__ bm1){
    __shared__ float4 SN[8][8];                     // sn per warp (32 floats)
    __shared__ float  SD[8][16];                    // per-edge dots
    __shared__ float4 WGC[8][16];                   // {wg, wc, mc, 0} per edge
    __shared__ float shred[4];                      // num, sas, denp0, denp1
    if (threadIdx.x < 4) shred[threadIdx.x] = 0.f;
    __syncthreads();

    int wid = (blockIdx.x*blockDim.x + threadIdx.x) >> 5;
    int lane = threadIdx.x & 31;
    int w = threadIdx.x >> 5;
    float4* wgc = WGC[w];
    int b = wid >> 10, bN = b << 10;
    int deg = g_deg[wid];
    const int* cols = g_cols + wid*MAXD;
    float f_n = g_srw[2*wid];
    float s1n = g_srw[2*wid+1];
    float sn  = g_sct[wid*KC + lane];
    float sqn = g_sqct[wid];
    float invvol = 1.f/(g_acc[ACC_VOL + b] + EPSV);
    float num_acc = 0.f, sas_acc = 0.f;
    float dg_acc = 0.f, dc_acc = 0.f;
    float y_gap0 = 0.f, y_ct0 = 0.f;       // lane = h (even edges)
    float y_gap1 = 0.f, y_ct1 = 0.f;       // (odd edges)

    // stage sn into smem once; each lane keeps its float4 slice in a register
    ((float*)SN[w])[lane] = sn;
    __syncwarp();
    int r8 = lane >> 3;        // 0..3 : row within 4-row group
    int p8 = lane & 7;         // 0..7 : float4 slot of the row
    float4 snr = SN[w][p8];    // register-resident sn slice (loop-invariant)
    int eh = lane & 15;        // edge within subtile
    int half = lane >> 4;

    for (int j0 = 0; j0 < deg; j0 += 16){
        int tlen = deg - j0; if (tlen > 16) tlen = 16;
        int jl = j0 + lane;
        int mycol = -1;
        if (jl < deg) mycol = cols[jl];
        // prefetch 4 row-slices (one per g), MLP=4
        float4 v[4];
        #pragma unroll
        for (int g = 0; g < 4; g++){
            int e = g*4 + r8;
            int mc = __shfl_sync(FULL, mycol, e);
            if (mc >= 0) v[g] = ((const float4*)(g_sct + (size_t)(bN+mc)*KC))[p8];
            else         v[g] = make_float4(0.f,0.f,0.f,0.f);
        }
        // 4 independent segment-reduced dots (8 consecutive lanes per row)
        #pragma unroll
        for (int g = 0; g < 4; g++){
            float pd = v[g].x*snr.x + v[g].y*snr.y + v[g].z*snr.z + v[g].w*snr.w;
            pd += __shfl_xor_sync(FULL, pd, 1);
            pd += __shfl_xor_sync(FULL, pd, 2);
            pd += __shfl_xor_sync(FULL, pd, 4);
            if (p8 == 0) SD[w][g*4 + r8] = pd;
        }
        __syncwarp();
        // per-edge weights on lanes 0..15
        int j = j0 + eh;
        bool act = (j < deg) && (half == 0);
        float wg = 0.f, wc = 0.f;
        int mc16 = __shfl_sync(FULL, mycol, eh);
        if (act){
            float dot = SD[w][eh];
            float4 ni = g_ninfo[bN + mc16];
            float d = f_n - ni.x;
            float q2 = sqn + ni.z - 2.f*dot;
            wg = 1.f - d*d;
            wc = sqrtf(fmaxf(q2, 0.f) + 1e-12f)*invvol;
            g_wgap[wid*MAXD + j] = wg;
            g_wct [wid*MAXD + j] = wc;
            num_acc += f_n*ni.x + s1n*ni.y;
            sas_acc += dot;
            dg_acc += wg; dc_acc += wc;
        }
        if (half == 0) wgc[eh] = make_float4(wg, wc, __int_as_float(mc16 < 0 ? 0 : mc16), 0.f);
        __syncwarp();
        // both-branch aggregation: dual accumulators break the FFMA chain
        #pragma unroll 4
        for (int jj = 0; jj < tlen; jj++){
            float4 q = wgc[jj];
            float xv = g_xh[(bN + __float_as_int(q.z))*H + lane];
            if (jj & 1){ y_gap1 += q.x*xv; y_ct1 += q.y*xv; }
            else       { y_gap0 += q.x*xv; y_ct0 += q.y*xv; }
        }
        __syncwarp();
    }
    float y_gap = y_gap0 + y_gap1;
    float y_ct  = y_ct0  + y_ct1;
    num_acc = wsum(num_acc);
    sas_acc = wsum(sas_acc);
    float dsum_g = wsum(dg_acc);
    float dsum_c = wsum(dc_acc);

    // lin + pool softmax for both branches (weights from global; L1-hit broadcast)
    float xh = g_xh[wid*H + lane];
    float den_g = 0.f, den_c = 0.f;
    #pragma unroll
    for (int br = 0; br < 2; br++){
        float y = br ? y_ct : y_gap;
        const float* brel = br ? br1 : br0;
        const float* bmc  = br ? bm1 : bm0;
        const float* Wr = br ? Wr1 : Wr0;
        const float* Wo = br ? Wo1 : Wo0;
        const float* Wm = br ? Wm1 : Wm0;
        float acc = brel[lane];
        #pragma unroll
        for (int j = 0; j < 32; j++){
            acc += __shfl_sync(FULL, y,  j) * Wr[j*H + lane];
            acc += __shfl_sync(FULL, xh, j) * Wo[j*H + lane];
        }
        g_xg[br*BN*H + wid*H + lane] = acc;
        float a = (lane < KM) ? bmc[lane] : 0.f;
        #pragma unroll
        for (int j = 0; j < 32; j++){
            float xj = __shfl_sync(FULL, acc, j);
            if (lane < KM) a += xj * Wm[j*KM + lane];
        }
        float mm = a;
        #pragma unroll
        for (int o = 8; o; o >>= 1) mm = fmaxf(mm, __shfl_xor_sync(FULL, mm, o, 16));
        float e = (lane < KM) ? expf(a - mm) : 0.f;
        float es = wsum16(e);
        float s = e/es;
        if (lane < KM) g_smc[br*BN*KM + wid*KM + lane] = s;
        float sq = wsum16(s*s);
        if (br) den_c = sq; else den_g = sq;
    }
    if (lane == 0){
        atomicAdd(&shred[0], num_acc);
        atomicAdd(&shred[1], sas_acc);
        atomicAdd(&shred[2], dsum_g*den_g);
        atomicAdd(&shred[3], dsum_c*den_c);
    }
    __syncthreads();
    if (threadIdx.x < 4){
        int bb = blockIdx.x >> 7;
        const int dst[4] = {ACC_NUMRW, ACC_SAS, ACC_DENP, ACC_DENP + B};
        atomicAdd(&g_acc[dst[threadIdx.x] + bb], shred[threadIdx.x]);
    }
}

// batch-staged pool: one block = (128-node chunk, batch, branch).
__global__ void k_pool(){
    extern __shared__ float smc_s[];       // N*KM = 16384 floats = 64KB
    __shared__ float st16[128*17];
    int c = blockIdx.x, b = blockIdx.y, br = blockIdx.z;
    int t = threadIdx.x;                   // 1024
    int w = t >> 5, lane = t & 31;
    int bN = b*N;
    const float* smc = g_smc + br*BN*KM;
    {
        float4* dst = (float4*)smc_s;
        const float4* src = (const float4*)(smc + bN*KM);
        #pragma unroll
        for (int i = 0; i < 4; i++) dst[t + i*1024] = src[t + i*1024];
    }
    __syncthreads();
    int half = lane >> 4, l16 = lane & 15;
    #pragma unroll
    for (int q = 0; q < 4; q++){
        int nl = c*128 + w*4 + q;          // local node in batch
        int r = bN + nl;
        int deg = g_deg[r];
        const int* cols = g_cols + r*MAXD;
        const float* w_arr = (br ? g_wct : g_wgap) + r*MAXD;
        float tacc = 0.f;
        #pragma unroll 2
        for (int j = half; j < deg; j += 2)
            tacc += w_arr[j] * smc_s[cols[j]*KM + l16];
        tacc += __shfl_down_sync(FULL, tacc, 16);
        if (lane < KM) st16[(w*4+q)*17 + l16] = tacc;
    }
    __syncthreads();
    int base = (br*B + b)*256;
    int n0 = c*128;
    if (t < 256){
        int k = t >> 4, l = t & 15;
        float oa = 0.f;
        #pragma unroll 4
        for (int n = 0; n < 128; n++)
            oa += smc_s[(n0+n)*KM + k] * st16[n*17 + l];
        atomicAdd(&g_acc[ACC_OA + base + t], oa);
    } else if (t < 512){
        int k = (t-256) >> 4, l = t & 15;
        float ssv = 0.f;
        #pragma unroll 4
        for (int n = 0; n < 128; n++)
            ssv += smc_s[(n0+n)*KM + k] * smc_s[(n0+n)*KM + l];
        atomicAdd(&g_acc[ACC_SSP + base + (t-256)], ssv);
    } else {
        int kk = (t-512) >> 5, h = t & 31;
        float px = 0.f;
        const float* xg = g_xg + br*BN*H + (size_t)(bN + n0)*H;
        #pragma unroll 4
        for (int n = 0; n < 128; n++)
            px += smc_s[(n0+n)*KM + kk] * xg[n*H + h];
        atomicAdd(&g_acc[ACC_PX + (br*B + b)*512 + (t-512)], px);
    }
}

// finalize pool: pool losses + normalized pooladj + pooled DGC; br==0 blocks
// additionally compute the CT ortho/ct/rw losses (merged k_ctfin).
__global__ void k_poolfin(const float* __restrict__ W2g_rel, const float* __restrict__ b2g,
                          const float* __restrict__ W2g_root){
    int b = blockIdx.x, br = blockIdx.y, t = threadIdx.x;   // 512
    __shared__ float oa[256], ssm[256], px[512], t2[512], pa[256], red[512], nrm_s;
    int base = (br*B + b)*256;
    if (t < 256){ oa[t] = g_acc[ACC_OA + base + t]; ssm[t] = g_acc[ACC_SSP + base + t]; }
    px[t] = g_acc[ACC_PX + (br*B + b)*512 + t];
    __syncthreads();
    red[t] = (t < 256) ? ssm[t]*ssm[t] : 0.f;
    __syncthreads();
    for (int o = 256; o; o >>= 1){ if (t < o) red[t] += red[t+o]; __syncthreads(); }
    if (t == 0) nrm_s = sqrtf(red[0]);
    __syncthreads();
    if (t < 256){
        int k = t >> 4, l = t & 15;
        float d = ssm[t]/nrm_s - ((k == l) ? 0.25f : 0.f);
        red[t] = d*d;
    } else red[t] = 0.f;
    __syncthreads();
    for (int o = 256; o; o >>= 1){ if (t < o) red[t] += red[t+o]; __syncthreads(); }
    if (t == 0){
        float num = 0.f;
        #pragma unroll
        for (int k = 0; k < KM; k++) num += oa[k*KM + k];
        float den = g_acc[ACC_DENP + br*B + b] + EPSV;
        atomicAdd(&g_acc[ACC_LOSS],   -(num/den)/(float)B);
        atomicAdd(&g_acc[ACC_LOSS+1], sqrtf(red[0])/(float)B);
    }
    __shared__ float dsq[KM];
    if (t < KM){
        float rs = 0.f;
        #pragma unroll
        for (int l = 0; l < KM; l++) rs += (l == t) ? 0.f : oa[t*KM + l];
        dsq[t] = sqrtf(rs) + EPSV;
    }
    __syncthreads();
    if (t < 256){
        int k = t >> 4, l = t & 15;
        pa[t] = (k == l) ? 0.f : oa[t]/(dsq[k]*dsq[l]);
    }
    __syncthreads();
    int k = t >> 5, h = t & 31;
    float a = 0.f;
    #pragma unroll
    for (int l = 0; l < KM; l++) a += pa[k*KM + l]*px[l*H + h];
    t2[t] = a;
    __syncthreads();
    float accv = b2g[h];
    #pragma unroll
    for (int j = 0; j < H; j++)
        accv += t2[k*H + j]*W2g_rel[j*H + h] + px[k*H + j]*W2g_root[j*H + h];
    g_x2[br*B*KM*H + b*KM*H + t] = accv;

    // ---- merged CT/rewiring losses (br==0 blocks only) ----
    if (br == 0){
        __syncthreads();
        float v1 = g_acc[ACC_SSCT + b*1024 + t];
        float v2 = g_acc[ACC_SSCT + b*1024 + t + 512];
        red[t] = v1*v1 + v2*v2;
        __syncthreads();
        for (int o = 256; o; o >>= 1){ if (t < o) red[t] += red[t+o]; __syncthreads(); }
        if (t == 0) nrm_s = sqrtf(red[0]);
        __syncthreads();
        float nrm = nrm_s;
        const float isk32 = 0.17677669529663687f;
        int e1 = t,       k1 = e1 >> 5, l1 = e1 & 31;
        int e2 = t + 512, k2 = e2 >> 5, l2 = e2 & 31;
        float d1 = v1/nrm - ((k1 == l1) ? isk32 : 0.f);
        float d2 = v2/nrm - ((k2 == l2) ? isk32 : 0.f);
        red[t] = d1*d1 + d2*d2;
        __syncthreads();
        for (int o = 256; o; o >>= 1){ if (t < o) red[t] += red[t+o]; __syncthreads(); }
        if (t == 0){
            float sas = g_acc[ACC_SAS + b];
            float den = g_acc[ACC_DENCT + b] + EPSV;
            float sds = g_acc[ACC_SDS + b];
            float lm = ((sds - sas)/den)/(float)B;
            float lo = sqrtf(red[0])/(float)B;
            float num = g_acc[ACC_NUMRW + b];
            float dnr = g_acc[ACC_DENRW + b] + EPSV;
            float s00 = g_acc[ACC_S00 + b];
            float s01 = g_acc[ACC_S01 + b];
            float s11 = g_acc[ACC_S11 + b];
            float nrm2 = sqrtf(s00*s00 + 2.f*s01*s01 + s11*s11);
            const float isk = 0.70710678118654752f;
            float d00 = s00/nrm2 - isk, d01 = s01/nrm2, d11 = s11/nrm2 - isk;
            lm += -(num/dnr)/(float)B;
            lo += sqrtf(d00*d00 + 2.f*d01*d01 + d11*d11)/(float)B;
            atomicAdd(&g_acc[ACC_LOSS],   lm);
            atomicAdd(&g_acc[ACC_LOSS+1], lo);
        }
    }
}

__global__ void k_readout(const float* __restrict__ Wcat, const float* __restrict__ bcat,
                          const float* __restrict__ W2,  const float* __restrict__ b2,
                          const float* __restrict__ W3,  const float* __restrict__ b3,
                          float* __restrict__ out){
    int b = blockIdx.x, h = threadIdx.x;   // 32
    __shared__ float h1[H], h2[H], lg[10];
    float acc = 0.f;
    for (int kk = 0; kk < KM; kk++){
        float z = bcat[h];
        #pragma unroll
        for (int j = 0; j < H; j++) z += g_x2[b*KM*H + kk*H + j]*Wcat[j*H + h];
        #pragma unroll
        for (int j = 0; j < H; j++) z += g_x2[B*KM*H + b*KM*H + kk*H + j]*Wcat[(H+j)*H + h];
        acc += fmaxf(z, 0.f);
    }
    h1[h] = acc; __syncwarp();
    float z2 = b2[h];
    #pragma unroll
    for (int j = 0; j < H; j++) z2 += h1[j]*W2[j*H + h];
    h2[h] = fmaxf(z2, 0.f); __syncwarp();
    if (h < 10){
        float z = b3[h];
        #pragma unroll
        for (int j = 0; j < H; j++) z += h2[j]*W3[j*10 + h];
        lg[h] = z;
    }
    __syncwarp();
    if (h < 10){
        float m = lg[0];
        #pragma unroll
        for (int i = 1; i < 10; i++) m = fmaxf(m, lg[i]);
        float s = 0.f;
        #pragma unroll
        for (int i = 0; i < 10; i++) s += expf(lg[i] - m);
        out[b*10 + h] = lg[h] - m - logf(s);
    }
    if (b == 0 && h == 31){
        out[B*10]     = g_acc[ACC_LOSS];
        out[B*10 + 1] = g_acc[ACC_LOSS+1];
    }
}

extern "C" void kernel_launch(void* const* d_in, const int* in_sizes, int n_in,
                              void* d_out, int out_size){
    const float* x      = (const float*)d_in[0];
    const float* adj    = (const float*)d_in[1];
    const float* W1     = (const float*)d_in[3];
    const float* b1     = (const float*)d_in[4];
    const float* Wrw    = (const float*)d_in[5];
    const float* brw    = (const float*)d_in[6];
    const float* Wg_rel = (const float*)d_in[7];
    const float* bg     = (const float*)d_in[8];
    const float* Wg_root= (const float*)d_in[9];
    const float* Wmcg   = (const float*)d_in[10];
    const float* bmcg   = (const float*)d_in[11];
    const float* W2g_rel= (const float*)d_in[12];
    const float* b2g    = (const float*)d_in[13];
    const float* W2g_root=(const float*)d_in[14];
    const float* Wct    = (const float*)d_in[15];
    const float* bct    = (const float*)d_in[16];
    const float* Wc_rel = (const float*)d_in[17];
    const float* bc     = (const float*)d_in[18];
    const float* Wc_root= (const float*)d_in[19];
    const float* Wmcc   = (const float*)d_in[20];
    const float* bmcc   = (const float*)d_in[21];
    const float* Wcat   = (const float*)d_in[22];
    const float* bcat   = (const float*)d_in[23];
    const float* W2     = (const float*)d_in[24];
    const float* b2     = (const float*)d_in[25];
    const float* W3     = (const float*)d_in[26];
    const float* b3     = (const float*)d_in[27];
    float* out = (float*)d_out;

    // one-time resources (created on the first, non-captured correctness call)
    static cudaStream_t s2 = 0;
    static cudaEvent_t evFork = 0, evJoin = 0;
    static bool inited = false;
    if (!inited){
        cudaStreamCreateWithFlags(&s2, cudaStreamNonBlocking);
        cudaEventCreateWithFlags(&evFork, cudaEventDisableTiming);
        cudaEventCreateWithFlags(&evJoin, cudaEventDisableTiming);
        cudaFuncSetAttribute(k_pool, cudaFuncAttributeMaxDynamicSharedMemorySize, 65536);
        inited = true;
    }

    k_init<<<(ACC_TOTAL+511)/512, 512>>>();
    k_build_soft<<<BN/8, 256>>>(adj, x, W1, b1, Wrw, brw, Wct, bct);

    // fork: ctpart runs concurrently with edgeagg + pool
    cudaEventRecord(evFork, 0);
    cudaStreamWaitEvent(s2, evFork, 0);
    k_ctpart<<<B*8, 1024, 0, s2>>>();

    k_edgeagg<<<BN/8, 256>>>(Wg_rel, bg, Wg_root, Wmcg, bmcg,
                             Wc_rel, bc, Wc_root, Wmcc, bmcc);
    k_pool<<<dim3(8, B, 2), 1024, 65536>>>();

    // join before poolfin (consumes SSCT from ctpart)
    cudaEventRecord(evJoin, s2);
    cudaStreamWaitEvent(0, evJoin, 0);

    k_poolfin<<<dim3(B, 2), 512>>>(W2g_rel, b2g, W2g_root);
    k_readout<<<B, 32>>>(Wcat, bcat, W2, b2, W3, b3, out);

    (void)in_sizes; (void)n_in; (void)out_size;
}